// round 14
// baseline (speedup 1.0000x reference)
#include <cuda_runtime.h>
#include <cuda_bf16.h>
#include <cstdint>
#include <math.h>

// ---------------------------------------------------------------------------
// Problem constants
// ---------------------------------------------------------------------------
#define NPTS   16384     // B*N
#define NSAMP  8192      // points per sample
#define CDIM   256
#define KNN    16
#define NPART  8
#define PARTLEN (NSAMP / NPART)   // 1024
#define RMAX   16        // kNN ring capacity

// kNN dynamic smem layout (bytes)
#define KS_TILE 0         // float4[128]  = 2048
#define KS_HD   2048      // float[2048]  = 8192
#define KS_HI   10240     // int[2048]    = 8192
#define KS_RD   18432     // float[2048]  = 8192
#define KS_RI   26624     // int[2048]    = 8192
#define KNN_SMEM_BYTES 34816

// ---------------------------------------------------------------------------
// Scratch (static __device__ — no allocation allowed)
// ---------------------------------------------------------------------------
__device__ float g_x[NPTS * CDIM];
__device__ float g_q[NPTS * CDIM];
__device__ float g_k[NPTS * CDIM];
__device__ float g_v[NPTS * CDIM];
__device__ float g_cd[NPTS * NPART * KNN];
__device__ int   g_ci[NPTS * NPART * KNN];
__device__ int   g_idx[NPTS * KNN];
__device__ __align__(16) __nv_bfloat16 g_xh[NPTS * CDIM];
__device__ __align__(16) __nv_bfloat16 g_xl[NPTS * CDIM];
__device__ __align__(16) __nv_bfloat16 g_wh[CDIM * 768];
__device__ __align__(16) __nv_bfloat16 g_wl[CDIM * 768];
__device__ __align__(16) __nv_bfloat16 g_w1h[CDIM * 32];
__device__ __align__(16) __nv_bfloat16 g_w1l[CDIM * 32];

// ---------------------------------------------------------------------------
// mma.sync + cp.async helpers
// ---------------------------------------------------------------------------
__device__ __forceinline__ unsigned int s2u(const void* p) {
    return (unsigned int)__cvta_generic_to_shared(p);
}
__device__ __forceinline__ void ldsm4(unsigned int* r, unsigned int a) {
    asm volatile("ldmatrix.sync.aligned.m8n8.x4.shared.b16 {%0,%1,%2,%3},[%4];"
        : "=r"(r[0]), "=r"(r[1]), "=r"(r[2]), "=r"(r[3]) : "r"(a));
}
__device__ __forceinline__ void ldsm4t(unsigned int* r, unsigned int a) {
    asm volatile("ldmatrix.sync.aligned.m8n8.x4.trans.shared.b16 {%0,%1,%2,%3},[%4];"
        : "=r"(r[0]), "=r"(r[1]), "=r"(r[2]), "=r"(r[3]) : "r"(a));
}
__device__ __forceinline__ void mma_bf16(float* c, const unsigned int* a,
                                         const unsigned int* b) {
    asm volatile("mma.sync.aligned.m16n8k16.row.col.f32.bf16.bf16.f32 "
        "{%0,%1,%2,%3},{%4,%5,%6,%7},{%8,%9},{%0,%1,%2,%3};"
        : "+f"(c[0]), "+f"(c[1]), "+f"(c[2]), "+f"(c[3])
        : "r"(a[0]), "r"(a[1]), "r"(a[2]), "r"(a[3]), "r"(b[0]), "r"(b[1]));
}
#define CP_ASYNC16(dst, src) \
    asm volatile("cp.async.cg.shared.global [%0],[%1],16;" :: "r"(dst), "l"(src))
#define CP_COMMIT() asm volatile("cp.async.commit_group;")
#define CP_WAIT(n)  asm volatile("cp.async.wait_group %0;" :: "n"(n))

// ---------------------------------------------------------------------------
// Weight bf16 hi/lo conversions
// ---------------------------------------------------------------------------
__global__ __launch_bounds__(256)
void convert_w_kernel(const float* __restrict__ Wq, const float* __restrict__ Wk,
                      const float* __restrict__ Wv)
{
    const int gid = blockIdx.x * 256 + threadIdx.x;
    const int k    = gid / 768;
    const int ncat = gid % 768;
    const int z = ncat >> 8;
    const int n = ncat & 255;
    const float* W = (z == 0) ? Wq : (z == 1) ? Wk : Wv;
    float v = W[k * 256 + n];
    __nv_bfloat16 hi = __float2bfloat16(v);
    __nv_bfloat16 lo = __float2bfloat16(v - __bfloat162float(hi));
    g_wh[k * 768 + ncat] = hi;
    g_wl[k * 768 + ncat] = lo;
}

__global__ __launch_bounds__(256)
void convert_w1_kernel(const float* __restrict__ Ww1)
{
    const int gid = blockIdx.x * 256 + threadIdx.x;   // 8192
    float v = Ww1[gid];
    __nv_bfloat16 hi = __float2bfloat16(v);
    g_w1h[gid] = hi;
    g_w1l[gid] = __float2bfloat16(v - __bfloat162float(hi));
}

// ---------------------------------------------------------------------------
// QKV tensor-core GEMM, bf16 hi/lo, 2-stage cp.async pipeline.
// ---------------------------------------------------------------------------
#define A_STRIDE 40
#define B_STRIDE 136
#define ST_AH 0
#define ST_AL 5120
#define ST_BH 10240
#define ST_BL 14592
#define ST_TOTAL 18944
#define QKV_SMEM_BYTES (2 * ST_TOTAL * 2)

__global__ __launch_bounds__(256)
void qkv_mma_kernel(const float* __restrict__ bq, const float* __restrict__ bk,
                    const float* __restrict__ bv,
                    float* __restrict__ Cq, float* __restrict__ Ck,
                    float* __restrict__ Cv)
{
    extern __shared__ __align__(16) __nv_bfloat16 qsm[];

    const int t    = threadIdx.x;
    const int lane = t & 31;
    const int warp = t >> 5;
    const int wm   = warp & 1;
    const int wn   = warp >> 1;
    const int m0   = blockIdx.x * 128;
    const int n0g  = blockIdx.y * 128;

    float acc[4][4][4];
#pragma unroll
    for (int i = 0; i < 4; i++)
#pragma unroll
        for (int j = 0; j < 4; j++)
#pragma unroll
            for (int l = 0; l < 4; l++) acc[i][j][l] = 0.f;

    auto issue_stage = [&](int it, int b) {
        const int k0 = it * 32;
        __nv_bfloat16* Ah = qsm + b * ST_TOTAL + ST_AH;
        __nv_bfloat16* Al = qsm + b * ST_TOTAL + ST_AL;
        __nv_bfloat16* Bh = qsm + b * ST_TOTAL + ST_BH;
        __nv_bfloat16* Bl = qsm + b * ST_TOTAL + ST_BL;
#pragma unroll
        for (int rep = 0; rep < 2; rep++) {
            int id = t + rep * 256;
            int arr = id >> 2, acc_ = id & 3;
            CP_ASYNC16(s2u(Ah + arr * A_STRIDE + acc_ * 8),
                       g_xh + (size_t)(m0 + arr) * 256 + k0 + acc_ * 8);
            CP_ASYNC16(s2u(Al + arr * A_STRIDE + acc_ * 8),
                       g_xl + (size_t)(m0 + arr) * 256 + k0 + acc_ * 8);
            int br = id >> 4, bc = id & 15;
            CP_ASYNC16(s2u(Bh + br * B_STRIDE + bc * 8),
                       g_wh + (size_t)(k0 + br) * 768 + n0g + bc * 8);
            CP_ASYNC16(s2u(Bl + br * B_STRIDE + bc * 8),
                       g_wl + (size_t)(k0 + br) * 768 + n0g + bc * 8);
        }
        CP_COMMIT();
    };

    issue_stage(0, 0);

#pragma unroll
    for (int it = 0; it < 8; it++) {
        const int b = it & 1;
        if (it + 1 < 8) { issue_stage(it + 1, b ^ 1); CP_WAIT(1); }
        else            { CP_WAIT(0); }
        __syncthreads();

        const __nv_bfloat16* Ah = qsm + b * ST_TOTAL + ST_AH;
        const __nv_bfloat16* Al = qsm + b * ST_TOTAL + ST_AL;
        const __nv_bfloat16* Bh = qsm + b * ST_TOTAL + ST_BH;
        const __nv_bfloat16* Bl = qsm + b * ST_TOTAL + ST_BL;

#pragma unroll
        for (int ks = 0; ks < 2; ks++) {
            unsigned int ah[4][4], al[4][4], bh[4][2], bl[4][2];
#pragma unroll
            for (int mm = 0; mm < 4; mm++) {
                int row = wm * 64 + mm * 16 + (lane & 15);
                int col = ks * 16 + (lane >> 4) * 8;
                ldsm4(&ah[mm][0], s2u(Ah + row * A_STRIDE + col));
                ldsm4(&al[mm][0], s2u(Al + row * A_STRIDE + col));
            }
#pragma unroll
            for (int nb = 0; nb < 2; nb++) {
                int kk = ks * 16 + (lane & 15);
                int nc = wn * 32 + nb * 16 + (lane >> 4) * 8;
                unsigned int r[4];
                ldsm4t(&r[0], s2u(Bh + kk * B_STRIDE + nc));
                bh[nb * 2][0] = r[0]; bh[nb * 2][1] = r[1];
                bh[nb * 2 + 1][0] = r[2]; bh[nb * 2 + 1][1] = r[3];
                ldsm4t(&r[0], s2u(Bl + kk * B_STRIDE + nc));
                bl[nb * 2][0] = r[0]; bl[nb * 2][1] = r[1];
                bl[nb * 2 + 1][0] = r[2]; bl[nb * 2 + 1][1] = r[3];
            }
#pragma unroll
            for (int mm = 0; mm < 4; mm++)
#pragma unroll
                for (int nn = 0; nn < 4; nn++) {
                    mma_bf16(&acc[mm][nn][0], &ah[mm][0], &bh[nn][0]);
                    mma_bf16(&acc[mm][nn][0], &ah[mm][0], &bl[nn][0]);
                    mma_bf16(&acc[mm][nn][0], &al[mm][0], &bh[nn][0]);
                }
        }
        __syncthreads();
    }

    const int z = n0g >> 8;
    const float* bias = (z == 0) ? bq : (z == 1) ? bk : bv;
    float* C          = (z == 0) ? Cq : (z == 1) ? Ck : Cv;
    const int ncol0 = n0g & 255;

#pragma unroll
    for (int mm = 0; mm < 4; mm++) {
#pragma unroll
        for (int nn = 0; nn < 4; nn++) {
            int rowg = m0 + wm * 64 + mm * 16 + (lane >> 2);
            int col  = ncol0 + wn * 32 + nn * 8 + (lane & 3) * 2;
            float b0 = bias[col], b1 = bias[col + 1];
            float2 v0 = make_float2(acc[mm][nn][0] + b0, acc[mm][nn][1] + b1);
            float2 v1 = make_float2(acc[mm][nn][2] + b0, acc[mm][nn][3] + b1);
            *(float2*)&C[(size_t)rowg * 256 + col]       = v0;
            *(float2*)&C[(size_t)(rowg + 8) * 256 + col] = v1;
        }
    }
}

// ---------------------------------------------------------------------------
// Embed SGEMM with fused bf16 hi/lo epilogue -> g_x, g_xh, g_xl
// ---------------------------------------------------------------------------
__global__ __launch_bounds__(256, 2)
void sgemm_embed_kernel(const float* __restrict__ A, const float* __restrict__ W,
                        const float* __restrict__ bias, float* __restrict__ C,
                        int coff)
{
    const int KD = 128, NW = 128;
    __shared__ float As[8 * 128];
    __shared__ float Bs[8 * 132];

    const int t  = threadIdx.x;
    const int bm = blockIdx.x * 128;

    const int arow = t >> 1;
    const int ak   = (t & 1) * 4;
    const int wkk  = t >> 5;
    const int wn   = (t & 31) * 4;
    const int ty = t >> 4;
    const int tx = t & 15;

    float acc[8][8];
#pragma unroll
    for (int i = 0; i < 8; i++)
#pragma unroll
        for (int j = 0; j < 8; j++) acc[i][j] = 0.f;

    const float* Aptr = A + (size_t)(bm + arow) * KD + ak;
    const float* Wptr = W + (size_t)wkk * NW + wn;

    float4 av = *(const float4*)Aptr;
    float4 wv = *(const float4*)Wptr;

    for (int k0 = 0; k0 < KD; k0 += 8) {
        As[(ak + 0) * 128 + arow] = av.x;
        As[(ak + 1) * 128 + arow] = av.y;
        As[(ak + 2) * 128 + arow] = av.z;
        As[(ak + 3) * 128 + arow] = av.w;
        *(float4*)&Bs[wkk * 132 + wn] = wv;
        __syncthreads();
        if (k0 + 8 < KD) {
            av = *(const float4*)(Aptr + k0 + 8);
            wv = *(const float4*)(Wptr + (size_t)(k0 + 8) * NW);
        }
#pragma unroll
        for (int kk = 0; kk < 8; kk++) {
            float4 a0 = *(const float4*)&As[kk * 128 + ty * 8];
            float4 a1 = *(const float4*)&As[kk * 128 + ty * 8 + 4];
            float4 b0 = *(const float4*)&Bs[kk * 132 + tx * 8];
            float4 b1 = *(const float4*)&Bs[kk * 132 + tx * 8 + 4];
            float ar[8] = {a0.x, a0.y, a0.z, a0.w, a1.x, a1.y, a1.z, a1.w};
            float br[8] = {b0.x, b0.y, b0.z, b0.w, b1.x, b1.y, b1.z, b1.w};
#pragma unroll
            for (int i = 0; i < 8; i++)
#pragma unroll
                for (int j = 0; j < 8; j++)
                    acc[i][j] = fmaf(ar[i], br[j], acc[i][j]);
        }
        __syncthreads();
    }

#pragma unroll
    for (int i = 0; i < 8; i++) {
        const size_t row = (size_t)(bm + ty * 8 + i);
        float* crow = C + row * CDIM + coff + tx * 8;
        float o[8];
#pragma unroll
        for (int j = 0; j < 8; j++) o[j] = acc[i][j] + bias[tx * 8 + j];
        *(float4*)(crow)     = make_float4(o[0], o[1], o[2], o[3]);
        *(float4*)(crow + 4) = make_float4(o[4], o[5], o[6], o[7]);
        __nv_bfloat16 h[8], l[8];
#pragma unroll
        for (int j = 0; j < 8; j++) {
            h[j] = __float2bfloat16(o[j]);
            l[j] = __float2bfloat16(o[j] - __bfloat162float(h[j]));
        }
        *(uint4*)&g_xh[row * CDIM + coff + tx * 8] = *(const uint4*)&h[0];
        *(uint4*)&g_xl[row * CDIM + coff + tx * 8] = *(const uint4*)&l[0];
    }
}

// ---------------------------------------------------------------------------
// kNN partial top-16, dynamic smem, NPART=8 (grid 1024 blocks — the fix
// for grid-starved occupancy measured at 20.5% across R8-R13).
// ---------------------------------------------------------------------------
__global__ __launch_bounds__(128)
void knn_kernel(const float* __restrict__ xyz)
{
    extern __shared__ __align__(16) char ksm[];
    float4* tile = (float4*)(ksm + KS_TILE);
    float*  hd   = (float*)(ksm + KS_HD);
    int*    hi   = (int*)(ksm + KS_HI);
    float*  rdq  = (float*)(ksm + KS_RD);
    int*    riq  = (int*)(ksm + KS_RI);

    const int t = threadIdx.x;
    const int i = blockIdx.x * 128 + t;

    const float m2x = -2.f * xyz[i * 3 + 0];
    const float m2y = -2.f * xyz[i * 3 + 1];
    const float m2z = -2.f * xyz[i * 3 + 2];

    const int base   = (i >> 13) << 13;
    const int jstart = base + blockIdx.y * PARTLEN;

    {
        int jg = jstart + t;
        float x = xyz[jg * 3 + 0];
        float y = xyz[jg * 3 + 1];
        float z = xyz[jg * 3 + 2];
        tile[t] = make_float4(x, y, z, x * x + y * y + z * z);
    }
    __syncthreads();

    float worst = -1e30f;
    int   ws = 0, cnt = 0;

#pragma unroll
    for (int s = 0; s < KNN; s++) {
        float4 f = tile[s];
        float d = fmaf(m2x, f.x, fmaf(m2y, f.y, fmaf(m2z, f.z, f.w)));
        hd[s * 128 + t] = d;
        hi[s * 128 + t] = jstart + s;
        if (d > worst) { worst = d; ws = s; }
    }

    auto consolidate = [&]() {
        for (int e = 0; e < cnt; e++) {
            float d = rdq[e * 128 + t];
            if (d < worst) {
                hd[ws * 128 + t] = d;
                hi[ws * 128 + t] = riq[e * 128 + t];
                worst = -1e30f;
#pragma unroll
                for (int s = 0; s < KNN; s++) {
                    float v = hd[s * 128 + t];
                    if (v > worst) { worst = v; ws = s; }
                }
            }
        }
        cnt = 0;
    };

    for (int jj = KNN; jj < 128; jj += 8) {
#pragma unroll
        for (int u = 0; u < 8; u++) {
            float4 f = tile[jj + u];
            float d = fmaf(m2x, f.x, fmaf(m2y, f.y, fmaf(m2z, f.z, f.w)));
            if (d < worst) {
                rdq[cnt * 128 + t] = d;
                riq[cnt * 128 + t] = jstart + jj + u;
                cnt++;
            }
        }
        if (__any_sync(0xffffffffu, cnt >= RMAX - 8)) consolidate();
    }

    for (int t0 = 128; t0 < PARTLEN; t0 += 128) {
        __syncthreads();
        {
            int jg = jstart + t0 + t;
            float x = xyz[jg * 3 + 0];
            float y = xyz[jg * 3 + 1];
            float z = xyz[jg * 3 + 2];
            tile[t] = make_float4(x, y, z, x * x + y * y + z * z);
        }
        __syncthreads();
        for (int jj = 0; jj < 128; jj += 8) {
#pragma unroll
            for (int u = 0; u < 8; u++) {
                float4 f = tile[jj + u];
                float d = fmaf(m2x, f.x, fmaf(m2y, f.y, fmaf(m2z, f.z, f.w)));
                if (d < worst) {
                    rdq[cnt * 128 + t] = d;
                    riq[cnt * 128 + t] = jstart + t0 + jj + u;
                    cnt++;
                }
            }
            if (__any_sync(0xffffffffu, cnt >= RMAX - 8)) consolidate();
        }
    }
    consolidate();

    const int ob = i * (NPART * KNN) + blockIdx.y * KNN;
#pragma unroll
    for (int s = 0; s < KNN; s++) {
        g_cd[ob + s] = hd[s * 128 + t];
        g_ci[ob + s] = hi[s * 128 + t];
    }
}

// ---------------------------------------------------------------------------
// kNN merge: one warp per point, 128 candidates (4/lane), shfl extract-min.
// ---------------------------------------------------------------------------
__global__ __launch_bounds__(256)
void knn_merge_kernel()
{
    const int gw   = (blockIdx.x * 256 + threadIdx.x) >> 5;
    const int lane = threadIdx.x & 31;

    float d[4];
    int   ix[4];
#pragma unroll
    for (int s = 0; s < 4; s++) {
        d[s]  = g_cd[gw * 128 + lane + 32 * s];
        ix[s] = g_ci[gw * 128 + lane + 32 * s];
    }

#pragma unroll
    for (int r = 0; r < KNN; r++) {
        float bm = d[0]; int bi = ix[0]; int which = 0;
#pragma unroll
        for (int s = 1; s < 4; s++)
            if (d[s] < bm) { bm = d[s]; bi = ix[s]; which = s; }
        int bl = lane;
#pragma unroll
        for (int off = 16; off; off >>= 1) {
            float om = __shfl_xor_sync(0xffffffffu, bm, off);
            int   oi = __shfl_xor_sync(0xffffffffu, bi, off);
            int   ol = __shfl_xor_sync(0xffffffffu, bl, off);
            if (om < bm || (om == bm && ol < bl)) { bm = om; bi = oi; bl = ol; }
        }
        if (lane == 0) g_idx[gw * KNN + r] = bi;
        if (bl == lane) d[which] = 3.4e38f;
    }
}

// ---------------------------------------------------------------------------
// Fused attention: 8 points/block (warp-per-point), mma logits.
// ---------------------------------------------------------------------------
#define AT_W1L  20480
#define AT_WW2  40960
#define AT_SCR  45056
#define AT_T3   81920
#define AT_JS   83968
#define ATTN_SMEM_BYTES 84480

#define FMA8(hs, u, vv, off)                               \
    acc[(off)+0] = fmaf(hs, u.x,  acc[(off)+0]);           \
    acc[(off)+1] = fmaf(hs, u.y,  acc[(off)+1]);           \
    acc[(off)+2] = fmaf(hs, u.z,  acc[(off)+2]);           \
    acc[(off)+3] = fmaf(hs, u.w,  acc[(off)+3]);           \
    acc[(off)+4] = fmaf(hs, vv.x, acc[(off)+4]);           \
    acc[(off)+5] = fmaf(hs, vv.y, acc[(off)+5]);           \
    acc[(off)+6] = fmaf(hs, vv.z, acc[(off)+6]);           \
    acc[(off)+7] = fmaf(hs, vv.w, acc[(off)+7]);

__global__ __launch_bounds__(256, 2)
void attn_kernel(
    const float* __restrict__ xyz,
    const float* __restrict__ Wp1, const float* __restrict__ bp1,
    const float* __restrict__ gp,  const float* __restrict__ betap,
    const float* __restrict__ Wp2, const float* __restrict__ bp2,
    const float* __restrict__ gw1, const float* __restrict__ betaw1,
    const float* __restrict__ bw1,
    const float* __restrict__ gw2, const float* __restrict__ betaw2,
    const float* __restrict__ Ww2, const float* __restrict__ bw2,
    float* __restrict__ out)
{
    extern __shared__ __align__(16) char smx[];
    __nv_bfloat16* W1Hs = (__nv_bfloat16*)smx;
    __nv_bfloat16* W1Ls = (__nv_bfloat16*)(smx + AT_W1L);
    float* Ww2s = (float*)(smx + AT_WW2);
    float* T3s  = (float*)(smx + AT_T3);
    int*   Js   = (int*)(smx + AT_JS);

    const int t = threadIdx.x;

    for (int i2 = t; i2 < 1024; i2 += 256) {
        int row = i2 >> 2, q = i2 & 3;
        *(uint4*)((char*)W1Hs + row * 80 + q * 16) =
            *(const uint4*)(g_w1h + row * 32 + q * 8);
        *(uint4*)((char*)W1Ls + row * 80 + q * 16) =
            *(const uint4*)(g_w1l + row * 32 + q * 8);
    }
    *(float4*)&Ww2s[t * 4] = *(const float4*)&Ww2[t * 4];

    const int w    = t >> 5;
    const int lane = t & 31;
    const int P    = blockIdx.x * 8 + w;
    char* scr = smx + AT_SCR + w * 4608;
    __nv_bfloat16* Hh = (__nv_bfloat16*)scr;             // [16][72]
    __nv_bfloat16* Hl = (__nv_bfloat16*)(scr + 2304);    // [16][72]

    const float pix = xyz[P * 3 + 0];
    const float piy = xyz[P * 3 + 1];
    const float piz = xyz[P * 3 + 2];
    if (lane < KNN) {
        int j = g_idx[P * KNN + lane];
        Js[w * 16 + lane] = j;
        float dx = xyz[j * 3 + 0] - pix;
        float dy = xyz[j * 3 + 1] - piy;
        float dz = xyz[j * 3 + 2] - piz;
        float a0 = dx * Wp1[0] + dy * Wp1[3] + dz * Wp1[6] + bp1[0];
        float a1 = dx * Wp1[1] + dy * Wp1[4] + dz * Wp1[7] + bp1[1];
        float a2 = dx * Wp1[2] + dy * Wp1[5] + dz * Wp1[8] + bp1[2];
        T3s[(w * 16 + lane) * 4 + 0] = fmaxf(fmaf(gp[0], a0, betap[0]), 0.f);
        T3s[(w * 16 + lane) * 4 + 1] = fmaxf(fmaf(gp[1], a1, betap[1]), 0.f);
        T3s[(w * 16 + lane) * 4 + 2] = fmaxf(fmaf(gp[2], a2, betap[2]), 0.f);
    }
    __syncthreads();

    float W0p[8], W1p[8], W2p[8], C0p[8], g1p[8];
#pragma unroll
    for (int cc = 0; cc < 8; cc++) {
        int c = cc * 32 + lane;
        float g = gw1[c];
        g1p[cc] = g;
        W0p[cc] = g * Wp2[c];
        W1p[cc] = g * Wp2[256 + c];
        W2p[cc] = g * Wp2[512 + c];
        C0p[cc] = fmaf(g, bp2[c] - g_q[(size_t)P * CDIM + c], betaw1[c]);
    }

    float acc[16];
#pragma unroll
    for (int i = 0; i < 16; i++) acc[i] = 0.f;

#pragma unroll
    for (int ch = 0; ch < 4; ch++) {
#pragma unroll 4
        for (int k = 0; k < KNN; k++) {
            int j = Js[w * 16 + k];
            float t0 = T3s[(w * 16 + k) * 4 + 0];
            float t1 = T3s[(w * 16 + k) * 4 + 1];
            float t2 = T3s[(w * 16 + k) * 4 + 2];
            const float* krow = g_k + (size_t)j * CDIM + ch * 64;
#pragma unroll
            for (int cc = 0; cc < 2; cc++) {
                int a = ch * 2 + cc;
                float kv = krow[cc * 32 + lane];
                float pr = fmaf(t0, W0p[a], fmaf(t1, W1p[a], fmaf(t2, W2p[a], C0p[a])));
                float hv = fmaxf(fmaf(g1p[a], kv, pr), 0.f);
                __nv_bfloat16 hhv = __float2bfloat16(hv);
                Hh[k * 72 + cc * 32 + lane] = hhv;
                Hl[k * 72 + cc * 32 + lane] =
                    __float2bfloat16(hv - __bfloat162float(hhv));
            }
        }
        __syncwarp();

#pragma unroll
        for (int kt = 0; kt < 4; kt++) {
            unsigned int ah[4], al[4], bh[4][2], bl[4][2];
            {
                int row = lane & 15;
                int colb = (kt * 16 + ((lane >> 4) << 3)) * 2;
                ldsm4(&ah[0], s2u((char*)Hh + row * 144 + colb));
                ldsm4(&al[0], s2u((char*)Hl + row * 144 + colb));
            }
            int krg = ch * 64 + kt * 16 + (lane & 15);
#pragma unroll
            for (int np = 0; np < 2; np++) {
                int nc = np * 16 + ((lane >> 4) << 3);
                unsigned int r[4];
                ldsm4t(&r[0], s2u((char*)W1Hs + (krg * 40 + nc) * 2));
                bh[np * 2][0] = r[0]; bh[np * 2][1] = r[1];
                bh[np * 2 + 1][0] = r[2]; bh[np * 2 + 1][1] = r[3];
                ldsm4t(&r[0], s2u((char*)W1Ls + (krg * 40 + nc) * 2));
                bl[np * 2][0] = r[0]; bl[np * 2][1] = r[1];
                bl[np * 2 + 1][0] = r[2]; bl[np * 2 + 1][1] = r[3];
            }
#pragma unroll
            for (int nt = 0; nt < 4; nt++) {
                mma_bf16(acc + nt * 4, &ah[0], &bh[nt][0]);
                mma_bf16(acc + nt * 4, &ah[0], &bl[nt][0]);
                mma_bf16(acc + nt * 4, &al[0], &bh[nt][0]);
            }
        }
        __syncwarp();
    }

    float* H2W = (float*)scr;
    {
        const int r0 = lane >> 2;
        const int cpair = (lane & 3) * 2;
#pragma unroll
        for (int nt = 0; nt < 4; nt++) {
            int cs = nt * 8 + cpair;
            float b0 = bw1[cs], b1 = bw1[cs + 1];
            float ga = gw2[cs], gb = gw2[cs + 1];
            float ba = betaw2[cs], bb = betaw2[cs + 1];
            float a00 = fmaxf(fmaf(ga, acc[nt * 4 + 0] + b0, ba), 0.f);
            float a01 = fmaxf(fmaf(gb, acc[nt * 4 + 1] + b1, bb), 0.f);
            float a10 = fmaxf(fmaf(ga, acc[nt * 4 + 2] + b0, ba), 0.f);
            float a11 = fmaxf(fmaf(gb, acc[nt * 4 + 3] + b1, bb), 0.f);
            *(float2*)&H2W[r0 * 36 + cs]       = make_float2(a00, a01);
            *(float2*)&H2W[(r0 + 8) * 36 + cs] = make_float2(a10, a11);
        }
    }
    __syncwarp();

    const int k0  = lane & 7;
    const int k1  = k0 + 8;
    const int cso = (lane >> 3) << 3;

#pragma unroll
    for (int i = 0; i < 16; i++) acc[i] = 0.f;
    {
        const float* x0p = H2W + k0 * 36;
        const float* x1p = H2W + k1 * 36;
#pragma unroll
        for (int cp = 0; cp < 32; cp += 4) {
            float4 ha = *(const float4*)(x0p + cp);
            float4 hb = *(const float4*)(x1p + cp);
            const float* wr = Ww2s + cp * 32 + cso;
            { const float4 u = *(const float4*)(wr); const float4 vv = *(const float4*)(wr + 4);
              FMA8(ha.x, u, vv, 0) FMA8(hb.x, u, vv, 8) }
            wr += 32;
            { const float4 u = *(const float4*)(wr); const float4 vv = *(const float4*)(wr + 4);
              FMA8(ha.y, u, vv, 0) FMA8(hb.y, u, vv, 8) }
            wr += 32;
            { const float4 u = *(const float4*)(wr); const float4 vv = *(const float4*)(wr + 4);
              FMA8(ha.z, u, vv, 0) FMA8(hb.z, u, vv, 8) }
            wr += 32;
            { const float4 u = *(const float4*)(wr); const float4 vv = *(const float4*)(wr + 4);
              FMA8(ha.w, u, vv, 0) FMA8(hb.w, u, vv, 8) }
        }
    }
    __syncwarp();

    float* WgW = (float*)scr;
    {
        float wa[8], wb[8];
#pragma unroll
        for (int i = 0; i < 8; i++) {
            int cs = cso + i;
            float la = acc[i]     + bw2[cs];
            float lb = acc[8 + i] + bw2[cs];
            float m = fmaxf(la, lb);
            m = fmaxf(m, __shfl_xor_sync(0xffffffffu, m, 1));
            m = fmaxf(m, __shfl_xor_sync(0xffffffffu, m, 2));
            m = fmaxf(m, __shfl_xor_sync(0xffffffffu, m, 4));
            float ea = __expf(la - m);
            float eb = __expf(lb - m);
            float s = ea + eb;
            s += __shfl_xor_sync(0xffffffffu, s, 1);
            s += __shfl_xor_sync(0xffffffffu, s, 2);
            s += __shfl_xor_sync(0xffffffffu, s, 4);
            float inv = 1.f / s;
            wa[i] = ea * inv;
            wb[i] = eb * inv;
        }
#pragma unroll
        for (int i = 0; i < 8; i++) {
            WgW[(cso + i) * 20 + k0] = wa[i];
            WgW[(cso + i) * 20 + k1] = wb[i];
        }
    }
    __syncwarp();

    float wk[16];
    {
        const float* wp = WgW + lane * 20;
        *(float4*)&wk[0]  = *(const float4*)(wp);
        *(float4*)&wk[4]  = *(const float4*)(wp + 4);
        *(float4*)&wk[8]  = *(const float4*)(wp + 8);
        *(float4*)&wk[12] = *(const float4*)(wp + 12);
    }

    float W0o[8], W1o[8], W2o[8], bpo[8], acc3[8];
#pragma unroll
    for (int cc = 0; cc < 8; cc++) {
        int c = cc * 32 + lane;
        W0o[cc] = Wp2[c];
        W1o[cc] = Wp2[256 + c];
        W2o[cc] = Wp2[512 + c];
        bpo[cc] = bp2[c];
        acc3[cc] = g_x[(size_t)P * CDIM + c];
    }

#pragma unroll 4
    for (int k = 0; k < KNN; k++) {
        int j = Js[w * 16 + k];
        float t0 = T3s[(w * 16 + k) * 4 + 0];
        float t1 = T3s[(w * 16 + k) * 4 + 1];
        float t2 = T3s[(w * 16 + k) * 4 + 2];
        const float* vrow = g_v + (size_t)j * CDIM;
        float wgt = wk[k];
#pragma unroll
        for (int cc = 0; cc < 8; cc++) {
            int c = cc * 32 + lane;
            float pr = fmaf(t0, W0o[cc], fmaf(t1, W1o[cc], fmaf(t2, W2o[cc], bpo[cc])));
            acc3[cc] = fmaf(vrow[c] + pr, wgt, acc3[cc]);
        }
    }

#pragma unroll
    for (int cc = 0; cc < 8; cc++)
        out[(size_t)P * CDIM + cc * 32 + lane] = acc3[cc];
}

// ---------------------------------------------------------------------------
// Launch — knn at index 3 (the profiled slot)
// ---------------------------------------------------------------------------
extern "C" void kernel_launch(void* const* d_in, const int* in_sizes, int n_in,
                              void* d_out, int out_size)
{
    const float* x_main = (const float*)d_in[0];
    const float* x_mod  = (const float*)d_in[1];
    const float* xyz    = (const float*)d_in[2];
    const float* We2d   = (const float*)d_in[3];
    const float* be2d   = (const float*)d_in[4];
    const float* We3d   = (const float*)d_in[5];
    const float* be3d   = (const float*)d_in[6];
    const float* Wq     = (const float*)d_in[7];
    const float* bq     = (const float*)d_in[8];
    const float* Wk     = (const float*)d_in[9];
    const float* bk     = (const float*)d_in[10];
    const float* Wv     = (const float*)d_in[11];
    const float* bv     = (const float*)d_in[12];
    const float* Wp1    = (const float*)d_in[13];
    const float* bp1    = (const float*)d_in[14];
    const float* gp     = (const float*)d_in[15];
    const float* betap  = (const float*)d_in[16];
    const float* Wp2    = (const float*)d_in[17];
    const float* bp2    = (const float*)d_in[18];
    const float* gw1    = (const float*)d_in[19];
    const float* betaw1 = (const float*)d_in[20];
    const float* Ww1    = (const float*)d_in[21];
    const float* bw1    = (const float*)d_in[22];
    const float* gw2    = (const float*)d_in[23];
    const float* betaw2 = (const float*)d_in[24];
    const float* Ww2    = (const float*)d_in[25];
    const float* bw2    = (const float*)d_in[26];
    float* out = (float*)d_out;

    float *dx, *dq, *dk, *dv;
    cudaGetSymbolAddress((void**)&dx, g_x);
    cudaGetSymbolAddress((void**)&dq, g_q);
    cudaGetSymbolAddress((void**)&dk, g_k);
    cudaGetSymbolAddress((void**)&dv, g_v);

    cudaFuncSetAttribute(qkv_mma_kernel, cudaFuncAttributeMaxDynamicSharedMemorySize,
                         QKV_SMEM_BYTES);
    cudaFuncSetAttribute(attn_kernel, cudaFuncAttributeMaxDynamicSharedMemorySize,
                         ATTN_SMEM_BYTES);
    cudaFuncSetAttribute(knn_kernel, cudaFuncAttributeMaxDynamicSharedMemorySize,
                         KNN_SMEM_BYTES);

    // 0,1: embed (+ fused bf16 conversion)
    sgemm_embed_kernel<<<dim3(NPTS / 128, 1), 256>>>(x_main, We3d, be3d, dx, 0);
    sgemm_embed_kernel<<<dim3(NPTS / 128, 1), 256>>>(x_mod,  We2d, be2d, dx, 128);

    // 2: qkv weight conversion
    convert_w_kernel<<<CDIM * 768 / 256, 256>>>(Wq, Wk, Wv);

    // 3: kNN partials (profiled slot, NPART=8 -> 1024 blocks), 4: merge
    knn_kernel<<<dim3(NPTS / 128, NPART), 128, KNN_SMEM_BYTES>>>(xyz);
    knn_merge_kernel<<<NPTS * 32 / 256, 256>>>();

    // 5: tensor-core qkv
    qkv_mma_kernel<<<dim3(NPTS / 128, 6), 256, QKV_SMEM_BYTES>>>(bq, bk, bv, dq, dk, dv);

    // 6: Ww1 conversion
    convert_w1_kernel<<<CDIM * 32 / 256, 256>>>(Ww1);

    // 7: fused attention (mma logits)
    attn_kernel<<<NPTS / 8, 256, ATTN_SMEM_BYTES>>>(
        xyz, Wp1, bp1, gp, betap, Wp2, bp2, gw1, betaw1,
        bw1, gw2, betaw2, Ww2, bw2, out);
}

// round 15
// speedup vs baseline: 1.0250x; 1.0250x over previous
#include <cuda_runtime.h>
#include <cuda_bf16.h>
#include <cstdint>
#include <math.h>

// ---------------------------------------------------------------------------
// Problem constants
// ---------------------------------------------------------------------------
#define NPTS   16384     // B*N
#define NSAMP  8192      // points per sample
#define CDIM   256
#define KNN    16
#define NPART  4
#define PARTLEN (NSAMP / NPART)   // 2048
#define RMAX   16        // kNN ring capacity

// kNN dynamic smem layout (bytes)
#define KS_TILE 0         // float4[128]  = 2048
#define KS_HD   2048      // float[2048]  = 8192
#define KS_HI   10240     // int[2048]    = 8192
#define KS_RD   18432     // float[2048]  = 8192
#define KS_RI   26624     // int[2048]    = 8192
#define KNN_SMEM_BYTES 34816

// ---------------------------------------------------------------------------
// Scratch (static __device__ — no allocation allowed)
// ---------------------------------------------------------------------------
__device__ float g_x[NPTS * CDIM];
__device__ float g_q[NPTS * CDIM];
__device__ float g_k[NPTS * CDIM];
__device__ float g_v[NPTS * CDIM];
__device__ float g_cd[NPTS * NPART * KNN];
__device__ int   g_ci[NPTS * NPART * KNN];
__device__ int   g_idx[NPTS * KNN];
__device__ __align__(16) __nv_bfloat16 g_xh[NPTS * CDIM];
__device__ __align__(16) __nv_bfloat16 g_xl[NPTS * CDIM];
__device__ __align__(16) __nv_bfloat16 g_wh[CDIM * 768];
__device__ __align__(16) __nv_bfloat16 g_wl[CDIM * 768];
__device__ __align__(16) __nv_bfloat16 g_w1h[CDIM * 32];
__device__ __align__(16) __nv_bfloat16 g_w1l[CDIM * 32];

// ---------------------------------------------------------------------------
// mma.sync + cp.async helpers
// ---------------------------------------------------------------------------
__device__ __forceinline__ unsigned int s2u(const void* p) {
    return (unsigned int)__cvta_generic_to_shared(p);
}
__device__ __forceinline__ void ldsm4(unsigned int* r, unsigned int a) {
    asm volatile("ldmatrix.sync.aligned.m8n8.x4.shared.b16 {%0,%1,%2,%3},[%4];"
        : "=r"(r[0]), "=r"(r[1]), "=r"(r[2]), "=r"(r[3]) : "r"(a));
}
__device__ __forceinline__ void ldsm4t(unsigned int* r, unsigned int a) {
    asm volatile("ldmatrix.sync.aligned.m8n8.x4.trans.shared.b16 {%0,%1,%2,%3},[%4];"
        : "=r"(r[0]), "=r"(r[1]), "=r"(r[2]), "=r"(r[3]) : "r"(a));
}
__device__ __forceinline__ void mma_bf16(float* c, const unsigned int* a,
                                         const unsigned int* b) {
    asm volatile("mma.sync.aligned.m16n8k16.row.col.f32.bf16.bf16.f32 "
        "{%0,%1,%2,%3},{%4,%5,%6,%7},{%8,%9},{%0,%1,%2,%3};"
        : "+f"(c[0]), "+f"(c[1]), "+f"(c[2]), "+f"(c[3])
        : "r"(a[0]), "r"(a[1]), "r"(a[2]), "r"(a[3]), "r"(b[0]), "r"(b[1]));
}
#define CP_ASYNC16(dst, src) \
    asm volatile("cp.async.cg.shared.global [%0],[%1],16;" :: "r"(dst), "l"(src))
#define CP_COMMIT() asm volatile("cp.async.commit_group;")
#define CP_WAIT(n)  asm volatile("cp.async.wait_group %0;" :: "n"(n))

// ---------------------------------------------------------------------------
// Weight bf16 hi/lo conversions
// ---------------------------------------------------------------------------
__global__ __launch_bounds__(256)
void convert_w_kernel(const float* __restrict__ Wq, const float* __restrict__ Wk,
                      const float* __restrict__ Wv)
{
    const int gid = blockIdx.x * 256 + threadIdx.x;
    const int k    = gid / 768;
    const int ncat = gid % 768;
    const int z = ncat >> 8;
    const int n = ncat & 255;
    const float* W = (z == 0) ? Wq : (z == 1) ? Wk : Wv;
    float v = W[k * 256 + n];
    __nv_bfloat16 hi = __float2bfloat16(v);
    __nv_bfloat16 lo = __float2bfloat16(v - __bfloat162float(hi));
    g_wh[k * 768 + ncat] = hi;
    g_wl[k * 768 + ncat] = lo;
}

__global__ __launch_bounds__(256)
void convert_w1_kernel(const float* __restrict__ Ww1)
{
    const int gid = blockIdx.x * 256 + threadIdx.x;   // 8192
    float v = Ww1[gid];
    __nv_bfloat16 hi = __float2bfloat16(v);
    g_w1h[gid] = hi;
    g_w1l[gid] = __float2bfloat16(v - __bfloat162float(hi));
}

// ---------------------------------------------------------------------------
// QKV tensor-core GEMM, bf16 hi/lo, 2-stage cp.async pipeline.
// ---------------------------------------------------------------------------
#define A_STRIDE 40
#define B_STRIDE 136
#define ST_AH 0
#define ST_AL 5120
#define ST_BH 10240
#define ST_BL 14592
#define ST_TOTAL 18944
#define QKV_SMEM_BYTES (2 * ST_TOTAL * 2)

__global__ __launch_bounds__(256)
void qkv_mma_kernel(const float* __restrict__ bq, const float* __restrict__ bk,
                    const float* __restrict__ bv,
                    float* __restrict__ Cq, float* __restrict__ Ck,
                    float* __restrict__ Cv)
{
    extern __shared__ __align__(16) __nv_bfloat16 qsm[];

    const int t    = threadIdx.x;
    const int lane = t & 31;
    const int warp = t >> 5;
    const int wm   = warp & 1;
    const int wn   = warp >> 1;
    const int m0   = blockIdx.x * 128;
    const int n0g  = blockIdx.y * 128;

    float acc[4][4][4];
#pragma unroll
    for (int i = 0; i < 4; i++)
#pragma unroll
        for (int j = 0; j < 4; j++)
#pragma unroll
            for (int l = 0; l < 4; l++) acc[i][j][l] = 0.f;

    auto issue_stage = [&](int it, int b) {
        const int k0 = it * 32;
        __nv_bfloat16* Ah = qsm + b * ST_TOTAL + ST_AH;
        __nv_bfloat16* Al = qsm + b * ST_TOTAL + ST_AL;
        __nv_bfloat16* Bh = qsm + b * ST_TOTAL + ST_BH;
        __nv_bfloat16* Bl = qsm + b * ST_TOTAL + ST_BL;
#pragma unroll
        for (int rep = 0; rep < 2; rep++) {
            int id = t + rep * 256;
            int arr = id >> 2, acc_ = id & 3;
            CP_ASYNC16(s2u(Ah + arr * A_STRIDE + acc_ * 8),
                       g_xh + (size_t)(m0 + arr) * 256 + k0 + acc_ * 8);
            CP_ASYNC16(s2u(Al + arr * A_STRIDE + acc_ * 8),
                       g_xl + (size_t)(m0 + arr) * 256 + k0 + acc_ * 8);
            int br = id >> 4, bc = id & 15;
            CP_ASYNC16(s2u(Bh + br * B_STRIDE + bc * 8),
                       g_wh + (size_t)(k0 + br) * 768 + n0g + bc * 8);
            CP_ASYNC16(s2u(Bl + br * B_STRIDE + bc * 8),
                       g_wl + (size_t)(k0 + br) * 768 + n0g + bc * 8);
        }
        CP_COMMIT();
    };

    issue_stage(0, 0);

#pragma unroll
    for (int it = 0; it < 8; it++) {
        const int b = it & 1;
        if (it + 1 < 8) { issue_stage(it + 1, b ^ 1); CP_WAIT(1); }
        else            { CP_WAIT(0); }
        __syncthreads();

        const __nv_bfloat16* Ah = qsm + b * ST_TOTAL + ST_AH;
        const __nv_bfloat16* Al = qsm + b * ST_TOTAL + ST_AL;
        const __nv_bfloat16* Bh = qsm + b * ST_TOTAL + ST_BH;
        const __nv_bfloat16* Bl = qsm + b * ST_TOTAL + ST_BL;

#pragma unroll
        for (int ks = 0; ks < 2; ks++) {
            unsigned int ah[4][4], al[4][4], bh[4][2], bl[4][2];
#pragma unroll
            for (int mm = 0; mm < 4; mm++) {
                int row = wm * 64 + mm * 16 + (lane & 15);
                int col = ks * 16 + (lane >> 4) * 8;
                ldsm4(&ah[mm][0], s2u(Ah + row * A_STRIDE + col));
                ldsm4(&al[mm][0], s2u(Al + row * A_STRIDE + col));
            }
#pragma unroll
            for (int nb = 0; nb < 2; nb++) {
                int kk = ks * 16 + (lane & 15);
                int nc = wn * 32 + nb * 16 + (lane >> 4) * 8;
                unsigned int r[4];
                ldsm4t(&r[0], s2u(Bh + kk * B_STRIDE + nc));
                bh[nb * 2][0] = r[0]; bh[nb * 2][1] = r[1];
                bh[nb * 2 + 1][0] = r[2]; bh[nb * 2 + 1][1] = r[3];
                ldsm4t(&r[0], s2u(Bl + kk * B_STRIDE + nc));
                bl[nb * 2][0] = r[0]; bl[nb * 2][1] = r[1];
                bl[nb * 2 + 1][0] = r[2]; bl[nb * 2 + 1][1] = r[3];
            }
#pragma unroll
            for (int mm = 0; mm < 4; mm++)
#pragma unroll
                for (int nn = 0; nn < 4; nn++) {
                    mma_bf16(&acc[mm][nn][0], &ah[mm][0], &bh[nn][0]);
                    mma_bf16(&acc[mm][nn][0], &ah[mm][0], &bl[nn][0]);
                    mma_bf16(&acc[mm][nn][0], &al[mm][0], &bh[nn][0]);
                }
        }
        __syncthreads();
    }

    const int z = n0g >> 8;
    const float* bias = (z == 0) ? bq : (z == 1) ? bk : bv;
    float* C          = (z == 0) ? Cq : (z == 1) ? Ck : Cv;
    const int ncol0 = n0g & 255;

#pragma unroll
    for (int mm = 0; mm < 4; mm++) {
#pragma unroll
        for (int nn = 0; nn < 4; nn++) {
            int rowg = m0 + wm * 64 + mm * 16 + (lane >> 2);
            int col  = ncol0 + wn * 32 + nn * 8 + (lane & 3) * 2;
            float b0 = bias[col], b1 = bias[col + 1];
            float2 v0 = make_float2(acc[mm][nn][0] + b0, acc[mm][nn][1] + b1);
            float2 v1 = make_float2(acc[mm][nn][2] + b0, acc[mm][nn][3] + b1);
            *(float2*)&C[(size_t)rowg * 256 + col]       = v0;
            *(float2*)&C[(size_t)(rowg + 8) * 256 + col] = v1;
        }
    }
}

// ---------------------------------------------------------------------------
// Embed SGEMM with fused bf16 hi/lo epilogue -> g_x, g_xh, g_xl
// ---------------------------------------------------------------------------
__global__ __launch_bounds__(256, 2)
void sgemm_embed_kernel(const float* __restrict__ A, const float* __restrict__ W,
                        const float* __restrict__ bias, float* __restrict__ C,
                        int coff)
{
    const int KD = 128, NW = 128;
    __shared__ float As[8 * 128];
    __shared__ float Bs[8 * 132];

    const int t  = threadIdx.x;
    const int bm = blockIdx.x * 128;

    const int arow = t >> 1;
    const int ak   = (t & 1) * 4;
    const int wkk  = t >> 5;
    const int wn   = (t & 31) * 4;
    const int ty = t >> 4;
    const int tx = t & 15;

    float acc[8][8];
#pragma unroll
    for (int i = 0; i < 8; i++)
#pragma unroll
        for (int j = 0; j < 8; j++) acc[i][j] = 0.f;

    const float* Aptr = A + (size_t)(bm + arow) * KD + ak;
    const float* Wptr = W + (size_t)wkk * NW + wn;

    float4 av = *(const float4*)Aptr;
    float4 wv = *(const float4*)Wptr;

    for (int k0 = 0; k0 < KD; k0 += 8) {
        As[(ak + 0) * 128 + arow] = av.x;
        As[(ak + 1) * 128 + arow] = av.y;
        As[(ak + 2) * 128 + arow] = av.z;
        As[(ak + 3) * 128 + arow] = av.w;
        *(float4*)&Bs[wkk * 132 + wn] = wv;
        __syncthreads();
        if (k0 + 8 < KD) {
            av = *(const float4*)(Aptr + k0 + 8);
            wv = *(const float4*)(Wptr + (size_t)(k0 + 8) * NW);
        }
#pragma unroll
        for (int kk = 0; kk < 8; kk++) {
            float4 a0 = *(const float4*)&As[kk * 128 + ty * 8];
            float4 a1 = *(const float4*)&As[kk * 128 + ty * 8 + 4];
            float4 b0 = *(const float4*)&Bs[kk * 132 + tx * 8];
            float4 b1 = *(const float4*)&Bs[kk * 132 + tx * 8 + 4];
            float ar[8] = {a0.x, a0.y, a0.z, a0.w, a1.x, a1.y, a1.z, a1.w};
            float br[8] = {b0.x, b0.y, b0.z, b0.w, b1.x, b1.y, b1.z, b1.w};
#pragma unroll
            for (int i = 0; i < 8; i++)
#pragma unroll
                for (int j = 0; j < 8; j++)
                    acc[i][j] = fmaf(ar[i], br[j], acc[i][j]);
        }
        __syncthreads();
    }

#pragma unroll
    for (int i = 0; i < 8; i++) {
        const size_t row = (size_t)(bm + ty * 8 + i);
        float* crow = C + row * CDIM + coff + tx * 8;
        float o[8];
#pragma unroll
        for (int j = 0; j < 8; j++) o[j] = acc[i][j] + bias[tx * 8 + j];
        *(float4*)(crow)     = make_float4(o[0], o[1], o[2], o[3]);
        *(float4*)(crow + 4) = make_float4(o[4], o[5], o[6], o[7]);
        __nv_bfloat16 h[8], l[8];
#pragma unroll
        for (int j = 0; j < 8; j++) {
            h[j] = __float2bfloat16(o[j]);
            l[j] = __float2bfloat16(o[j] - __bfloat162float(h[j]));
        }
        *(uint4*)&g_xh[row * CDIM + coff + tx * 8] = *(const uint4*)&h[0];
        *(uint4*)&g_xl[row * CDIM + coff + tx * 8] = *(const uint4*)&l[0];
    }
}

// ---------------------------------------------------------------------------
// kNN partial top-16 (R13 measured-best config: NPART=4, dynamic smem).
// ---------------------------------------------------------------------------
__global__ __launch_bounds__(128)
void knn_kernel(const float* __restrict__ xyz)
{
    extern __shared__ __align__(16) char ksm[];
    float4* tile = (float4*)(ksm + KS_TILE);
    float*  hd   = (float*)(ksm + KS_HD);
    int*    hi   = (int*)(ksm + KS_HI);
    float*  rdq  = (float*)(ksm + KS_RD);
    int*    riq  = (int*)(ksm + KS_RI);

    const int t = threadIdx.x;
    const int i = blockIdx.x * 128 + t;

    const float m2x = -2.f * xyz[i * 3 + 0];
    const float m2y = -2.f * xyz[i * 3 + 1];
    const float m2z = -2.f * xyz[i * 3 + 2];

    const int base   = (i >> 13) << 13;
    const int jstart = base + blockIdx.y * PARTLEN;

    {
        int jg = jstart + t;
        float x = xyz[jg * 3 + 0];
        float y = xyz[jg * 3 + 1];
        float z = xyz[jg * 3 + 2];
        tile[t] = make_float4(x, y, z, x * x + y * y + z * z);
    }
    __syncthreads();

    float worst = -1e30f;
    int   ws = 0, cnt = 0;

#pragma unroll
    for (int s = 0; s < KNN; s++) {
        float4 f = tile[s];
        float d = fmaf(m2x, f.x, fmaf(m2y, f.y, fmaf(m2z, f.z, f.w)));
        hd[s * 128 + t] = d;
        hi[s * 128 + t] = jstart + s;
        if (d > worst) { worst = d; ws = s; }
    }

    auto consolidate = [&]() {
        for (int e = 0; e < cnt; e++) {
            float d = rdq[e * 128 + t];
            if (d < worst) {
                hd[ws * 128 + t] = d;
                hi[ws * 128 + t] = riq[e * 128 + t];
                worst = -1e30f;
#pragma unroll
                for (int s = 0; s < KNN; s++) {
                    float v = hd[s * 128 + t];
                    if (v > worst) { worst = v; ws = s; }
                }
            }
        }
        cnt = 0;
    };

    for (int jj = KNN; jj < 128; jj += 8) {
#pragma unroll
        for (int u = 0; u < 8; u++) {
            float4 f = tile[jj + u];
            float d = fmaf(m2x, f.x, fmaf(m2y, f.y, fmaf(m2z, f.z, f.w)));
            if (d < worst) {
                rdq[cnt * 128 + t] = d;
                riq[cnt * 128 + t] = jstart + jj + u;
                cnt++;
            }
        }
        if (__any_sync(0xffffffffu, cnt >= RMAX - 8)) consolidate();
    }

    for (int t0 = 128; t0 < PARTLEN; t0 += 128) {
        __syncthreads();
        {
            int jg = jstart + t0 + t;
            float x = xyz[jg * 3 + 0];
            float y = xyz[jg * 3 + 1];
            float z = xyz[jg * 3 + 2];
            tile[t] = make_float4(x, y, z, x * x + y * y + z * z);
        }
        __syncthreads();
        for (int jj = 0; jj < 128; jj += 8) {
#pragma unroll
            for (int u = 0; u < 8; u++) {
                float4 f = tile[jj + u];
                float d = fmaf(m2x, f.x, fmaf(m2y, f.y, fmaf(m2z, f.z, f.w)));
                if (d < worst) {
                    rdq[cnt * 128 + t] = d;
                    riq[cnt * 128 + t] = jstart + t0 + jj + u;
                    cnt++;
                }
            }
            if (__any_sync(0xffffffffu, cnt >= RMAX - 8)) consolidate();
        }
    }
    consolidate();

    const int ob = i * (NPART * KNN) + blockIdx.y * KNN;
#pragma unroll
    for (int s = 0; s < KNN; s++) {
        g_cd[ob + s] = hd[s * 128 + t];
        g_ci[ob + s] = hi[s * 128 + t];
    }
}

// ---------------------------------------------------------------------------
// kNN merge: one warp per point, 64 candidates (2/lane), shfl extract-min.
// ---------------------------------------------------------------------------
__global__ __launch_bounds__(256)
void knn_merge_kernel()
{
    const int gw   = (blockIdx.x * 256 + threadIdx.x) >> 5;
    const int lane = threadIdx.x & 31;

    float d0 = g_cd[gw * 64 + lane];
    float d1 = g_cd[gw * 64 + lane + 32];
    int   i0 = g_ci[gw * 64 + lane];
    int   i1 = g_ci[gw * 64 + lane + 32];

#pragma unroll
    for (int r = 0; r < KNN; r++) {
        int   which;
        float bm; int bi;
        if (d0 <= d1) { bm = d0; bi = i0; which = 0; }
        else          { bm = d1; bi = i1; which = 1; }
        int bl = lane;
#pragma unroll
        for (int off = 16; off; off >>= 1) {
            float om = __shfl_xor_sync(0xffffffffu, bm, off);
            int   oi = __shfl_xor_sync(0xffffffffu, bi, off);
            int   ol = __shfl_xor_sync(0xffffffffu, bl, off);
            if (om < bm || (om == bm && ol < bl)) { bm = om; bi = oi; bl = ol; }
        }
        if (lane == 0) g_idx[gw * KNN + r] = bi;
        if (bl == lane) {
            if (which == 0) d0 = 3.4e38f; else d1 = 3.4e38f;
        }
    }
}

// ---------------------------------------------------------------------------
// Fused attention: 8 points/block (warp-per-point), mma logits.
// Phase 1/3 gathers vectorized to float2 (lane covers channels
// c = ch*64 + 2*lane + {0,1}; H column = channel-within-chunk preserved).
// ---------------------------------------------------------------------------
#define AT_W1L  20480
#define AT_WW2  40960
#define AT_SCR  45056
#define AT_T3   81920
#define AT_JS   83968
#define ATTN_SMEM_BYTES 84480

#define FMA8(hs, u, vv, off)                               \
    acc[(off)+0] = fmaf(hs, u.x,  acc[(off)+0]);           \
    acc[(off)+1] = fmaf(hs, u.y,  acc[(off)+1]);           \
    acc[(off)+2] = fmaf(hs, u.z,  acc[(off)+2]);           \
    acc[(off)+3] = fmaf(hs, u.w,  acc[(off)+3]);           \
    acc[(off)+4] = fmaf(hs, vv.x, acc[(off)+4]);           \
    acc[(off)+5] = fmaf(hs, vv.y, acc[(off)+5]);           \
    acc[(off)+6] = fmaf(hs, vv.z, acc[(off)+6]);           \
    acc[(off)+7] = fmaf(hs, vv.w, acc[(off)+7]);

__global__ __launch_bounds__(256, 2)
void attn_kernel(
    const float* __restrict__ xyz,
    const float* __restrict__ Wp1, const float* __restrict__ bp1,
    const float* __restrict__ gp,  const float* __restrict__ betap,
    const float* __restrict__ Wp2, const float* __restrict__ bp2,
    const float* __restrict__ gw1, const float* __restrict__ betaw1,
    const float* __restrict__ bw1,
    const float* __restrict__ gw2, const float* __restrict__ betaw2,
    const float* __restrict__ Ww2, const float* __restrict__ bw2,
    float* __restrict__ out)
{
    extern __shared__ __align__(16) char smx[];
    __nv_bfloat16* W1Hs = (__nv_bfloat16*)smx;
    __nv_bfloat16* W1Ls = (__nv_bfloat16*)(smx + AT_W1L);
    float* Ww2s = (float*)(smx + AT_WW2);
    float* T3s  = (float*)(smx + AT_T3);
    int*   Js   = (int*)(smx + AT_JS);

    const int t = threadIdx.x;

    for (int i2 = t; i2 < 1024; i2 += 256) {
        int row = i2 >> 2, q = i2 & 3;
        *(uint4*)((char*)W1Hs + row * 80 + q * 16) =
            *(const uint4*)(g_w1h + row * 32 + q * 8);
        *(uint4*)((char*)W1Ls + row * 80 + q * 16) =
            *(const uint4*)(g_w1l + row * 32 + q * 8);
    }
    *(float4*)&Ww2s[t * 4] = *(const float4*)&Ww2[t * 4];

    const int w    = t >> 5;
    const int lane = t & 31;
    const int P    = blockIdx.x * 8 + w;
    char* scr = smx + AT_SCR + w * 4608;
    __nv_bfloat16* Hh = (__nv_bfloat16*)scr;             // [16][72]
    __nv_bfloat16* Hl = (__nv_bfloat16*)(scr + 2304);    // [16][72]

    const float pix = xyz[P * 3 + 0];
    const float piy = xyz[P * 3 + 1];
    const float piz = xyz[P * 3 + 2];
    if (lane < KNN) {
        int j = g_idx[P * KNN + lane];
        Js[w * 16 + lane] = j;
        float dx = xyz[j * 3 + 0] - pix;
        float dy = xyz[j * 3 + 1] - piy;
        float dz = xyz[j * 3 + 2] - piz;
        float a0 = dx * Wp1[0] + dy * Wp1[3] + dz * Wp1[6] + bp1[0];
        float a1 = dx * Wp1[1] + dy * Wp1[4] + dz * Wp1[7] + bp1[1];
        float a2 = dx * Wp1[2] + dy * Wp1[5] + dz * Wp1[8] + bp1[2];
        T3s[(w * 16 + lane) * 4 + 0] = fmaxf(fmaf(gp[0], a0, betap[0]), 0.f);
        T3s[(w * 16 + lane) * 4 + 1] = fmaxf(fmaf(gp[1], a1, betap[1]), 0.f);
        T3s[(w * 16 + lane) * 4 + 2] = fmaxf(fmaf(gp[2], a2, betap[2]), 0.f);
    }
    __syncthreads();

    // per-lane channel constants: cc = ch*2+parity, c = ch*64 + 2*lane + parity
    float W0p[8], W1p[8], W2p[8], C0p[8], g1p[8];
#pragma unroll
    for (int cc = 0; cc < 8; cc++) {
        int c = (cc >> 1) * 64 + lane * 2 + (cc & 1);
        float g = gw1[c];
        g1p[cc] = g;
        W0p[cc] = g * Wp2[c];
        W1p[cc] = g * Wp2[256 + c];
        W2p[cc] = g * Wp2[512 + c];
        C0p[cc] = fmaf(g, bp2[c] - g_q[(size_t)P * CDIM + c], betaw1[c]);
    }

    float acc[16];
#pragma unroll
    for (int i = 0; i < 16; i++) acc[i] = 0.f;

#pragma unroll
    for (int ch = 0; ch < 4; ch++) {
        const int a0 = ch * 2, a1 = ch * 2 + 1;
#pragma unroll 4
        for (int k = 0; k < KNN; k++) {
            int j = Js[w * 16 + k];
            float t0 = T3s[(w * 16 + k) * 4 + 0];
            float t1 = T3s[(w * 16 + k) * 4 + 1];
            float t2 = T3s[(w * 16 + k) * 4 + 2];
            float2 kv = *(const float2*)(g_k + (size_t)j * CDIM + ch * 64 + lane * 2);
            float pr0 = fmaf(t0, W0p[a0], fmaf(t1, W1p[a0], fmaf(t2, W2p[a0], C0p[a0])));
            float hv0 = fmaxf(fmaf(g1p[a0], kv.x, pr0), 0.f);
            float pr1 = fmaf(t0, W0p[a1], fmaf(t1, W1p[a1], fmaf(t2, W2p[a1], C0p[a1])));
            float hv1 = fmaxf(fmaf(g1p[a1], kv.y, pr1), 0.f);
            __nv_bfloat16 h0 = __float2bfloat16(hv0);
            __nv_bfloat16 h1 = __float2bfloat16(hv1);
            __nv_bfloat162 hh; hh.x = h0; hh.y = h1;
            *(__nv_bfloat162*)(Hh + k * 72 + lane * 2) = hh;
            __nv_bfloat162 hl;
            hl.x = __float2bfloat16(hv0 - __bfloat162float(h0));
            hl.y = __float2bfloat16(hv1 - __bfloat162float(h1));
            *(__nv_bfloat162*)(Hl + k * 72 + lane * 2) = hl;
        }
        __syncwarp();

#pragma unroll
        for (int kt = 0; kt < 4; kt++) {
            unsigned int ah[4], al[4], bh[4][2], bl[4][2];
            {
                int row = lane & 15;
                int colb = (kt * 16 + ((lane >> 4) << 3)) * 2;
                ldsm4(&ah[0], s2u((char*)Hh + row * 144 + colb));
                ldsm4(&al[0], s2u((char*)Hl + row * 144 + colb));
            }
            int krg = ch * 64 + kt * 16 + (lane & 15);
#pragma unroll
            for (int np = 0; np < 2; np++) {
                int nc = np * 16 + ((lane >> 4) << 3);
                unsigned int r[4];
                ldsm4t(&r[0], s2u((char*)W1Hs + (krg * 40 + nc) * 2));
                bh[np * 2][0] = r[0]; bh[np * 2][1] = r[1];
                bh[np * 2 + 1][0] = r[2]; bh[np * 2 + 1][1] = r[3];
                ldsm4t(&r[0], s2u((char*)W1Ls + (krg * 40 + nc) * 2));
                bl[np * 2][0] = r[0]; bl[np * 2][1] = r[1];
                bl[np * 2 + 1][0] = r[2]; bl[np * 2 + 1][1] = r[3];
            }
#pragma unroll
            for (int nt = 0; nt < 4; nt++) {
                mma_bf16(acc + nt * 4, &ah[0], &bh[nt][0]);
                mma_bf16(acc + nt * 4, &ah[0], &bl[nt][0]);
                mma_bf16(acc + nt * 4, &al[0], &bh[nt][0]);
            }
        }
        __syncwarp();
    }

    float* H2W = (float*)scr;
    {
        const int r0 = lane >> 2;
        const int cpair = (lane & 3) * 2;
#pragma unroll
        for (int nt = 0; nt < 4; nt++) {
            int cs = nt * 8 + cpair;
            float b0 = bw1[cs], b1 = bw1[cs + 1];
            float ga = gw2[cs], gb = gw2[cs + 1];
            float ba = betaw2[cs], bb = betaw2[cs + 1];
            float a00 = fmaxf(fmaf(ga, acc[nt * 4 + 0] + b0, ba), 0.f);
            float a01 = fmaxf(fmaf(gb, acc[nt * 4 + 1] + b1, bb), 0.f);
            float a10 = fmaxf(fmaf(ga, acc[nt * 4 + 2] + b0, ba), 0.f);
            float a11 = fmaxf(fmaf(gb, acc[nt * 4 + 3] + b1, bb), 0.f);
            *(float2*)&H2W[r0 * 36 + cs]       = make_float2(a00, a01);
            *(float2*)&H2W[(r0 + 8) * 36 + cs] = make_float2(a10, a11);
        }
    }
    __syncwarp();

    const int k0  = lane & 7;
    const int k1  = k0 + 8;
    const int cso = (lane >> 3) << 3;

#pragma unroll
    for (int i = 0; i < 16; i++) acc[i] = 0.f;
    {
        const float* x0p = H2W + k0 * 36;
        const float* x1p = H2W + k1 * 36;
#pragma unroll
        for (int cp = 0; cp < 32; cp += 4) {
            float4 ha = *(const float4*)(x0p + cp);
            float4 hb = *(const float4*)(x1p + cp);
            const float* wr = Ww2s + cp * 32 + cso;
            { const float4 u = *(const float4*)(wr); const float4 vv = *(const float4*)(wr + 4);
              FMA8(ha.x, u, vv, 0) FMA8(hb.x, u, vv, 8) }
            wr += 32;
            { const float4 u = *(const float4*)(wr); const float4 vv = *(const float4*)(wr + 4);
              FMA8(ha.y, u, vv, 0) FMA8(hb.y, u, vv, 8) }
            wr += 32;
            { const float4 u = *(const float4*)(wr); const float4 vv = *(const float4*)(wr + 4);
              FMA8(ha.z, u, vv, 0) FMA8(hb.z, u, vv, 8) }
            wr += 32;
            { const float4 u = *(const float4*)(wr); const float4 vv = *(const float4*)(wr + 4);
              FMA8(ha.w, u, vv, 0) FMA8(hb.w, u, vv, 8) }
        }
    }
    __syncwarp();

    float* WgW = (float*)scr;
    {
        float wa[8], wb[8];
#pragma unroll
        for (int i = 0; i < 8; i++) {
            int cs = cso + i;
            float la = acc[i]     + bw2[cs];
            float lb = acc[8 + i] + bw2[cs];
            float m = fmaxf(la, lb);
            m = fmaxf(m, __shfl_xor_sync(0xffffffffu, m, 1));
            m = fmaxf(m, __shfl_xor_sync(0xffffffffu, m, 2));
            m = fmaxf(m, __shfl_xor_sync(0xffffffffu, m, 4));
            float ea = __expf(la - m);
            float eb = __expf(lb - m);
            float s = ea + eb;
            s += __shfl_xor_sync(0xffffffffu, s, 1);
            s += __shfl_xor_sync(0xffffffffu, s, 2);
            s += __shfl_xor_sync(0xffffffffu, s, 4);
            float inv = 1.f / s;
            wa[i] = ea * inv;
            wb[i] = eb * inv;
        }
#pragma unroll
        for (int i = 0; i < 8; i++) {
            WgW[(cso + i) * 20 + k0] = wa[i];
            WgW[(cso + i) * 20 + k1] = wb[i];
        }
    }
    __syncwarp();

    // per-lane softmax weights for cs = c & 31; with c = q4*64 + 2*lane + p,
    // cs depends only on (2*lane+p) & 31 — same for all q4. Load both parities.
    float wkA[16], wkB[16];
    {
        const float* wpA = WgW + ((lane * 2) & 31) * 20;
        const float* wpB = WgW + ((lane * 2 + 1) & 31) * 20;
#pragma unroll
        for (int q = 0; q < 4; q++) {
            *(float4*)&wkA[q * 4] = *(const float4*)(wpA + q * 4);
            *(float4*)&wkB[q * 4] = *(const float4*)(wpB + q * 4);
        }
    }

    // Phase 3 (float2): c = q4*64 + 2*lane + parity
    float W0o[8], W1o[8], W2o[8], bpo[8];
    float2 acc3[4];
#pragma unroll
    for (int cc = 0; cc < 8; cc++) {
        int c = (cc >> 1) * 64 + lane * 2 + (cc & 1);
        W0o[cc] = Wp2[c];
        W1o[cc] = Wp2[256 + c];
        W2o[cc] = Wp2[512 + c];
        bpo[cc] = bp2[c];
    }
#pragma unroll
    for (int q4 = 0; q4 < 4; q4++)
        acc3[q4] = *(const float2*)(g_x + (size_t)P * CDIM + q4 * 64 + lane * 2);

#pragma unroll 4
    for (int k = 0; k < KNN; k++) {
        int j = Js[w * 16 + k];
        float t0 = T3s[(w * 16 + k) * 4 + 0];
        float t1 = T3s[(w * 16 + k) * 4 + 1];
        float t2 = T3s[(w * 16 + k) * 4 + 2];
        const float* vrow = g_v + (size_t)j * CDIM;
        float wgA = wkA[k];
        float wgB = wkB[k];
#pragma unroll
        for (int q4 = 0; q4 < 4; q4++) {
            int a0 = q4 * 2, a1 = q4 * 2 + 1;
            float2 vv = *(const float2*)(vrow + q4 * 64 + lane * 2);
            float pr0 = fmaf(t0, W0o[a0], fmaf(t1, W1o[a0], fmaf(t2, W2o[a0], bpo[a0])));
            float pr1 = fmaf(t0, W0o[a1], fmaf(t1, W1o[a1], fmaf(t2, W2o[a1], bpo[a1])));
            acc3[q4].x = fmaf(vv.x + pr0, wgA, acc3[q4].x);
            acc3[q4].y = fmaf(vv.y + pr1, wgB, acc3[q4].y);
        }
    }

#pragma unroll
    for (int q4 = 0; q4 < 4; q4++)
        *(float2*)(out + (size_t)P * CDIM + q4 * 64 + lane * 2) = acc3[q4];
}

// ---------------------------------------------------------------------------
// Launch — knn at index 3 (the profiled slot)
// ---------------------------------------------------------------------------
extern "C" void kernel_launch(void* const* d_in, const int* in_sizes, int n_in,
                              void* d_out, int out_size)
{
    const float* x_main = (const float*)d_in[0];
    const float* x_mod  = (const float*)d_in[1];
    const float* xyz    = (const float*)d_in[2];
    const float* We2d   = (const float*)d_in[3];
    const float* be2d   = (const float*)d_in[4];
    const float* We3d   = (const float*)d_in[5];
    const float* be3d   = (const float*)d_in[6];
    const float* Wq     = (const float*)d_in[7];
    const float* bq     = (const float*)d_in[8];
    const float* Wk     = (const float*)d_in[9];
    const float* bk     = (const float*)d_in[10];
    const float* Wv     = (const float*)d_in[11];
    const float* bv     = (const float*)d_in[12];
    const float* Wp1    = (const float*)d_in[13];
    const float* bp1    = (const float*)d_in[14];
    const float* gp     = (const float*)d_in[15];
    const float* betap  = (const float*)d_in[16];
    const float* Wp2    = (const float*)d_in[17];
    const float* bp2    = (const float*)d_in[18];
    const float* gw1    = (const float*)d_in[19];
    const float* betaw1 = (const float*)d_in[20];
    const float* Ww1    = (const float*)d_in[21];
    const float* bw1    = (const float*)d_in[22];
    const float* gw2    = (const float*)d_in[23];
    const float* betaw2 = (const float*)d_in[24];
    const float* Ww2    = (const float*)d_in[25];
    const float* bw2    = (const float*)d_in[26];
    float* out = (float*)d_out;

    float *dx, *dq, *dk, *dv;
    cudaGetSymbolAddress((void**)&dx, g_x);
    cudaGetSymbolAddress((void**)&dq, g_q);
    cudaGetSymbolAddress((void**)&dk, g_k);
    cudaGetSymbolAddress((void**)&dv, g_v);

    cudaFuncSetAttribute(qkv_mma_kernel, cudaFuncAttributeMaxDynamicSharedMemorySize,
                         QKV_SMEM_BYTES);
    cudaFuncSetAttribute(attn_kernel, cudaFuncAttributeMaxDynamicSharedMemorySize,
                         ATTN_SMEM_BYTES);
    cudaFuncSetAttribute(knn_kernel, cudaFuncAttributeMaxDynamicSharedMemorySize,
                         KNN_SMEM_BYTES);

    // 0,1: embed (+ fused bf16 conversion)
    sgemm_embed_kernel<<<dim3(NPTS / 128, 1), 256>>>(x_main, We3d, be3d, dx, 0);
    sgemm_embed_kernel<<<dim3(NPTS / 128, 1), 256>>>(x_mod,  We2d, be2d, dx, 128);

    // 2: qkv weight conversion
    convert_w_kernel<<<CDIM * 768 / 256, 256>>>(Wq, Wk, Wv);

    // 3: kNN partials (profiled slot, NPART=4), 4: merge
    knn_kernel<<<dim3(NPTS / 128, NPART), 128, KNN_SMEM_BYTES>>>(xyz);
    knn_merge_kernel<<<NPTS * 32 / 256, 256>>>();

    // 5: tensor-core qkv
    qkv_mma_kernel<<<dim3(NPTS / 128, 6), 256, QKV_SMEM_BYTES>>>(bq, bk, bv, dq, dk, dv);

    // 6: Ww1 conversion
    convert_w1_kernel<<<CDIM * 32 / 256, 256>>>(Ww1);

    // 7: fused attention (mma logits, float2 gathers)
    attn_kernel<<<NPTS / 8, 256, ATTN_SMEM_BYTES>>>(
        xyz, Wp1, bp1, gp, betap, Wp2, bp2, gw1, betaw1,
        bw1, gw2, betaw2, Ww2, bw2, out);
}

// round 16
// speedup vs baseline: 1.1129x; 1.0857x over previous
#include <cuda_runtime.h>
#include <cuda_bf16.h>
#include <cstdint>
#include <math.h>

// ---------------------------------------------------------------------------
// Problem constants
// ---------------------------------------------------------------------------
#define NPTS   16384     // B*N
#define NSAMP  8192      // points per sample
#define CDIM   256
#define KNN    16
#define NPART  4
#define PARTLEN (NSAMP / NPART)   // 2048
#define RMAX   16        // kNN ring capacity

// kNN dynamic smem layout (bytes)
#define KS_TILE 0
#define KS_HD   2048
#define KS_HI   10240
#define KS_RD   18432
#define KS_RI   26624
#define KNN_SMEM_BYTES 34816

// ---------------------------------------------------------------------------
// Scratch (static __device__ — no allocation allowed)
// ---------------------------------------------------------------------------
__device__ float g_x[NPTS * CDIM];
__device__ float g_q[NPTS * CDIM];
__device__ float g_k[NPTS * CDIM];
__device__ float g_v[NPTS * CDIM];
__device__ float g_cd[NPTS * NPART * KNN];
__device__ int   g_ci[NPTS * NPART * KNN];
__device__ int   g_idx[NPTS * KNN];
__device__ __align__(16) __nv_bfloat16 g_xh[NPTS * CDIM];
__device__ __align__(16) __nv_bfloat16 g_xl[NPTS * CDIM];
__device__ __align__(16) __nv_bfloat16 g_wh[CDIM * 768];
__device__ __align__(16) __nv_bfloat16 g_wl[CDIM * 768];
__device__ __align__(16) __nv_bfloat16 g_w1h[CDIM * 32];
__device__ __align__(16) __nv_bfloat16 g_w1l[CDIM * 32];

// ---------------------------------------------------------------------------
// mma.sync + cp.async helpers
// ---------------------------------------------------------------------------
__device__ __forceinline__ unsigned int s2u(const void* p) {
    return (unsigned int)__cvta_generic_to_shared(p);
}
__device__ __forceinline__ void ldsm4(unsigned int* r, unsigned int a) {
    asm volatile("ldmatrix.sync.aligned.m8n8.x4.shared.b16 {%0,%1,%2,%3},[%4];"
        : "=r"(r[0]), "=r"(r[1]), "=r"(r[2]), "=r"(r[3]) : "r"(a));
}
__device__ __forceinline__ void ldsm4t(unsigned int* r, unsigned int a) {
    asm volatile("ldmatrix.sync.aligned.m8n8.x4.trans.shared.b16 {%0,%1,%2,%3},[%4];"
        : "=r"(r[0]), "=r"(r[1]), "=r"(r[2]), "=r"(r[3]) : "r"(a));
}
__device__ __forceinline__ void mma_bf16(float* c, const unsigned int* a,
                                         const unsigned int* b) {
    asm volatile("mma.sync.aligned.m16n8k16.row.col.f32.bf16.bf16.f32 "
        "{%0,%1,%2,%3},{%4,%5,%6,%7},{%8,%9},{%0,%1,%2,%3};"
        : "+f"(c[0]), "+f"(c[1]), "+f"(c[2]), "+f"(c[3])
        : "r"(a[0]), "r"(a[1]), "r"(a[2]), "r"(a[3]), "r"(b[0]), "r"(b[1]));
}
#define CP_ASYNC16(dst, src) \
    asm volatile("cp.async.cg.shared.global [%0],[%1],16;" :: "r"(dst), "l"(src))
#define CP_COMMIT() asm volatile("cp.async.commit_group;")
#define CP_WAIT(n)  asm volatile("cp.async.wait_group %0;" :: "n"(n))

// ---------------------------------------------------------------------------
// Weight bf16 hi/lo conversions
// ---------------------------------------------------------------------------
__global__ __launch_bounds__(256)
void convert_w_kernel(const float* __restrict__ Wq, const float* __restrict__ Wk,
                      const float* __restrict__ Wv)
{
    const int gid = blockIdx.x * 256 + threadIdx.x;
    const int k    = gid / 768;
    const int ncat = gid % 768;
    const int z = ncat >> 8;
    const int n = ncat & 255;
    const float* W = (z == 0) ? Wq : (z == 1) ? Wk : Wv;
    float v = W[k * 256 + n];
    __nv_bfloat16 hi = __float2bfloat16(v);
    __nv_bfloat16 lo = __float2bfloat16(v - __bfloat162float(hi));
    g_wh[k * 768 + ncat] = hi;
    g_wl[k * 768 + ncat] = lo;
}

__global__ __launch_bounds__(256)
void convert_w1_kernel(const float* __restrict__ Ww1)
{
    const int gid = blockIdx.x * 256 + threadIdx.x;   // 8192
    float v = Ww1[gid];
    __nv_bfloat16 hi = __float2bfloat16(v);
    g_w1h[gid] = hi;
    g_w1l[gid] = __float2bfloat16(v - __bfloat162float(hi));
}

// ---------------------------------------------------------------------------
// QKV tensor-core GEMM, bf16 hi/lo, 2-stage cp.async pipeline.
// ---------------------------------------------------------------------------
#define A_STRIDE 40
#define B_STRIDE 136
#define ST_AH 0
#define ST_AL 5120
#define ST_BH 10240
#define ST_BL 14592
#define ST_TOTAL 18944
#define QKV_SMEM_BYTES (2 * ST_TOTAL * 2)

__global__ __launch_bounds__(256)
void qkv_mma_kernel(const float* __restrict__ bq, const float* __restrict__ bk,
                    const float* __restrict__ bv,
                    float* __restrict__ Cq, float* __restrict__ Ck,
                    float* __restrict__ Cv)
{
    extern __shared__ __align__(16) __nv_bfloat16 qsm[];

    const int t    = threadIdx.x;
    const int lane = t & 31;
    const int warp = t >> 5;
    const int wm   = warp & 1;
    const int wn   = warp >> 1;
    const int m0   = blockIdx.x * 128;
    const int n0g  = blockIdx.y * 128;

    float acc[4][4][4];
#pragma unroll
    for (int i = 0; i < 4; i++)
#pragma unroll
        for (int j = 0; j < 4; j++)
#pragma unroll
            for (int l = 0; l < 4; l++) acc[i][j][l] = 0.f;

    auto issue_stage = [&](int it, int b) {
        const int k0 = it * 32;
        __nv_bfloat16* Ah = qsm + b * ST_TOTAL + ST_AH;
        __nv_bfloat16* Al = qsm + b * ST_TOTAL + ST_AL;
        __nv_bfloat16* Bh = qsm + b * ST_TOTAL + ST_BH;
        __nv_bfloat16* Bl = qsm + b * ST_TOTAL + ST_BL;
#pragma unroll
        for (int rep = 0; rep < 2; rep++) {
            int id = t + rep * 256;
            int arr = id >> 2, acc_ = id & 3;
            CP_ASYNC16(s2u(Ah + arr * A_STRIDE + acc_ * 8),
                       g_xh + (size_t)(m0 + arr) * 256 + k0 + acc_ * 8);
            CP_ASYNC16(s2u(Al + arr * A_STRIDE + acc_ * 8),
                       g_xl + (size_t)(m0 + arr) * 256 + k0 + acc_ * 8);
            int br = id >> 4, bc = id & 15;
            CP_ASYNC16(s2u(Bh + br * B_STRIDE + bc * 8),
                       g_wh + (size_t)(k0 + br) * 768 + n0g + bc * 8);
            CP_ASYNC16(s2u(Bl + br * B_STRIDE + bc * 8),
                       g_wl + (size_t)(k0 + br) * 768 + n0g + bc * 8);
        }
        CP_COMMIT();
    };

    issue_stage(0, 0);

#pragma unroll
    for (int it = 0; it < 8; it++) {
        const int b = it & 1;
        if (it + 1 < 8) { issue_stage(it + 1, b ^ 1); CP_WAIT(1); }
        else            { CP_WAIT(0); }
        __syncthreads();

        const __nv_bfloat16* Ah = qsm + b * ST_TOTAL + ST_AH;
        const __nv_bfloat16* Al = qsm + b * ST_TOTAL + ST_AL;
        const __nv_bfloat16* Bh = qsm + b * ST_TOTAL + ST_BH;
        const __nv_bfloat16* Bl = qsm + b * ST_TOTAL + ST_BL;

#pragma unroll
        for (int ks = 0; ks < 2; ks++) {
            unsigned int ah[4][4], al[4][4], bh[4][2], bl[4][2];
#pragma unroll
            for (int mm = 0; mm < 4; mm++) {
                int row = wm * 64 + mm * 16 + (lane & 15);
                int col = ks * 16 + (lane >> 4) * 8;
                ldsm4(&ah[mm][0], s2u(Ah + row * A_STRIDE + col));
                ldsm4(&al[mm][0], s2u(Al + row * A_STRIDE + col));
            }
#pragma unroll
            for (int nb = 0; nb < 2; nb++) {
                int kk = ks * 16 + (lane & 15);
                int nc = wn * 32 + nb * 16 + (lane >> 4) * 8;
                unsigned int r[4];
                ldsm4t(&r[0], s2u(Bh + kk * B_STRIDE + nc));
                bh[nb * 2][0] = r[0]; bh[nb * 2][1] = r[1];
                bh[nb * 2 + 1][0] = r[2]; bh[nb * 2 + 1][1] = r[3];
                ldsm4t(&r[0], s2u(Bl + kk * B_STRIDE + nc));
                bl[nb * 2][0] = r[0]; bl[nb * 2][1] = r[1];
                bl[nb * 2 + 1][0] = r[2]; bl[nb * 2 + 1][1] = r[3];
            }
#pragma unroll
            for (int mm = 0; mm < 4; mm++)
#pragma unroll
                for (int nn = 0; nn < 4; nn++) {
                    mma_bf16(&acc[mm][nn][0], &ah[mm][0], &bh[nn][0]);
                    mma_bf16(&acc[mm][nn][0], &ah[mm][0], &bl[nn][0]);
                    mma_bf16(&acc[mm][nn][0], &al[mm][0], &bh[nn][0]);
                }
        }
        __syncthreads();
    }

    const int z = n0g >> 8;
    const float* bias = (z == 0) ? bq : (z == 1) ? bk : bv;
    float* C          = (z == 0) ? Cq : (z == 1) ? Ck : Cv;
    const int ncol0 = n0g & 255;

#pragma unroll
    for (int mm = 0; mm < 4; mm++) {
#pragma unroll
        for (int nn = 0; nn < 4; nn++) {
            int rowg = m0 + wm * 64 + mm * 16 + (lane >> 2);
            int col  = ncol0 + wn * 32 + nn * 8 + (lane & 3) * 2;
            float b0 = bias[col], b1 = bias[col + 1];
            float2 v0 = make_float2(acc[mm][nn][0] + b0, acc[mm][nn][1] + b1);
            float2 v1 = make_float2(acc[mm][nn][2] + b0, acc[mm][nn][3] + b1);
            *(float2*)&C[(size_t)rowg * 256 + col]       = v0;
            *(float2*)&C[(size_t)(rowg + 8) * 256 + col] = v1;
        }
    }
}

// ---------------------------------------------------------------------------
// Embed SGEMM with fused bf16 hi/lo epilogue -> g_x, g_xh, g_xl
// ---------------------------------------------------------------------------
__global__ __launch_bounds__(256, 2)
void sgemm_embed_kernel(const float* __restrict__ A, const float* __restrict__ W,
                        const float* __restrict__ bias, float* __restrict__ C,
                        int coff)
{
    const int KD = 128, NW = 128;
    __shared__ float As[8 * 128];
    __shared__ float Bs[8 * 132];

    const int t  = threadIdx.x;
    const int bm = blockIdx.x * 128;

    const int arow = t >> 1;
    const int ak   = (t & 1) * 4;
    const int wkk  = t >> 5;
    const int wn   = (t & 31) * 4;
    const int ty = t >> 4;
    const int tx = t & 15;

    float acc[8][8];
#pragma unroll
    for (int i = 0; i < 8; i++)
#pragma unroll
        for (int j = 0; j < 8; j++) acc[i][j] = 0.f;

    const float* Aptr = A + (size_t)(bm + arow) * KD + ak;
    const float* Wptr = W + (size_t)wkk * NW + wn;

    float4 av = *(const float4*)Aptr;
    float4 wv = *(const float4*)Wptr;

    for (int k0 = 0; k0 < KD; k0 += 8) {
        As[(ak + 0) * 128 + arow] = av.x;
        As[(ak + 1) * 128 + arow] = av.y;
        As[(ak + 2) * 128 + arow] = av.z;
        As[(ak + 3) * 128 + arow] = av.w;
        *(float4*)&Bs[wkk * 132 + wn] = wv;
        __syncthreads();
        if (k0 + 8 < KD) {
            av = *(const float4*)(Aptr + k0 + 8);
            wv = *(const float4*)(Wptr + (size_t)(k0 + 8) * NW);
        }
#pragma unroll
        for (int kk = 0; kk < 8; kk++) {
            float4 a0 = *(const float4*)&As[kk * 128 + ty * 8];
            float4 a1 = *(const float4*)&As[kk * 128 + ty * 8 + 4];
            float4 b0 = *(const float4*)&Bs[kk * 132 + tx * 8];
            float4 b1 = *(const float4*)&Bs[kk * 132 + tx * 8 + 4];
            float ar[8] = {a0.x, a0.y, a0.z, a0.w, a1.x, a1.y, a1.z, a1.w};
            float br[8] = {b0.x, b0.y, b0.z, b0.w, b1.x, b1.y, b1.z, b1.w};
#pragma unroll
            for (int i = 0; i < 8; i++)
#pragma unroll
                for (int j = 0; j < 8; j++)
                    acc[i][j] = fmaf(ar[i], br[j], acc[i][j]);
        }
        __syncthreads();
    }

#pragma unroll
    for (int i = 0; i < 8; i++) {
        const size_t row = (size_t)(bm + ty * 8 + i);
        float* crow = C + row * CDIM + coff + tx * 8;
        float o[8];
#pragma unroll
        for (int j = 0; j < 8; j++) o[j] = acc[i][j] + bias[tx * 8 + j];
        *(float4*)(crow)     = make_float4(o[0], o[1], o[2], o[3]);
        *(float4*)(crow + 4) = make_float4(o[4], o[5], o[6], o[7]);
        __nv_bfloat16 h[8], l[8];
#pragma unroll
        for (int j = 0; j < 8; j++) {
            h[j] = __float2bfloat16(o[j]);
            l[j] = __float2bfloat16(o[j] - __bfloat162float(h[j]));
        }
        *(uint4*)&g_xh[row * CDIM + coff + tx * 8] = *(const uint4*)&h[0];
        *(uint4*)&g_xl[row * CDIM + coff + tx * 8] = *(const uint4*)&l[0];
    }
}

// ---------------------------------------------------------------------------
// kNN partial top-16 (R13 measured-best config: NPART=4, dynamic smem).
// ---------------------------------------------------------------------------
__global__ __launch_bounds__(128)
void knn_kernel(const float* __restrict__ xyz)
{
    extern __shared__ __align__(16) char ksm[];
    float4* tile = (float4*)(ksm + KS_TILE);
    float*  hd   = (float*)(ksm + KS_HD);
    int*    hi   = (int*)(ksm + KS_HI);
    float*  rdq  = (float*)(ksm + KS_RD);
    int*    riq  = (int*)(ksm + KS_RI);

    const int t = threadIdx.x;
    const int i = blockIdx.x * 128 + t;

    const float m2x = -2.f * xyz[i * 3 + 0];
    const float m2y = -2.f * xyz[i * 3 + 1];
    const float m2z = -2.f * xyz[i * 3 + 2];

    const int base   = (i >> 13) << 13;
    const int jstart = base + blockIdx.y * PARTLEN;

    {
        int jg = jstart + t;
        float x = xyz[jg * 3 + 0];
        float y = xyz[jg * 3 + 1];
        float z = xyz[jg * 3 + 2];
        tile[t] = make_float4(x, y, z, x * x + y * y + z * z);
    }
    __syncthreads();

    float worst = -1e30f;
    int   ws = 0, cnt = 0;

#pragma unroll
    for (int s = 0; s < KNN; s++) {
        float4 f = tile[s];
        float d = fmaf(m2x, f.x, fmaf(m2y, f.y, fmaf(m2z, f.z, f.w)));
        hd[s * 128 + t] = d;
        hi[s * 128 + t] = jstart + s;
        if (d > worst) { worst = d; ws = s; }
    }

    auto consolidate = [&]() {
        for (int e = 0; e < cnt; e++) {
            float d = rdq[e * 128 + t];
            if (d < worst) {
                hd[ws * 128 + t] = d;
                hi[ws * 128 + t] = riq[e * 128 + t];
                worst = -1e30f;
#pragma unroll
                for (int s = 0; s < KNN; s++) {
                    float v = hd[s * 128 + t];
                    if (v > worst) { worst = v; ws = s; }
                }
            }
        }
        cnt = 0;
    };

    for (int jj = KNN; jj < 128; jj += 8) {
#pragma unroll
        for (int u = 0; u < 8; u++) {
            float4 f = tile[jj + u];
            float d = fmaf(m2x, f.x, fmaf(m2y, f.y, fmaf(m2z, f.z, f.w)));
            if (d < worst) {
                rdq[cnt * 128 + t] = d;
                riq[cnt * 128 + t] = jstart + jj + u;
                cnt++;
            }
        }
        if (__any_sync(0xffffffffu, cnt >= RMAX - 8)) consolidate();
    }

    for (int t0 = 128; t0 < PARTLEN; t0 += 128) {
        __syncthreads();
        {
            int jg = jstart + t0 + t;
            float x = xyz[jg * 3 + 0];
            float y = xyz[jg * 3 + 1];
            float z = xyz[jg * 3 + 2];
            tile[t] = make_float4(x, y, z, x * x + y * y + z * z);
        }
        __syncthreads();
        for (int jj = 0; jj < 128; jj += 8) {
#pragma unroll
            for (int u = 0; u < 8; u++) {
                float4 f = tile[jj + u];
                float d = fmaf(m2x, f.x, fmaf(m2y, f.y, fmaf(m2z, f.z, f.w)));
                if (d < worst) {
                    rdq[cnt * 128 + t] = d;
                    riq[cnt * 128 + t] = jstart + t0 + jj + u;
                    cnt++;
                }
            }
            if (__any_sync(0xffffffffu, cnt >= RMAX - 8)) consolidate();
        }
    }
    consolidate();

    const int ob = i * (NPART * KNN) + blockIdx.y * KNN;
#pragma unroll
    for (int s = 0; s < KNN; s++) {
        g_cd[ob + s] = hd[s * 128 + t];
        g_ci[ob + s] = hi[s * 128 + t];
    }
}

// ---------------------------------------------------------------------------
// kNN merge: one warp per point, 64 candidates (2/lane), shfl extract-min.
// ---------------------------------------------------------------------------
__global__ __launch_bounds__(256)
void knn_merge_kernel()
{
    const int gw   = (blockIdx.x * 256 + threadIdx.x) >> 5;
    const int lane = threadIdx.x & 31;

    float d0 = g_cd[gw * 64 + lane];
    float d1 = g_cd[gw * 64 + lane + 32];
    int   i0 = g_ci[gw * 64 + lane];
    int   i1 = g_ci[gw * 64 + lane + 32];

#pragma unroll
    for (int r = 0; r < KNN; r++) {
        int   which;
        float bm; int bi;
        if (d0 <= d1) { bm = d0; bi = i0; which = 0; }
        else          { bm = d1; bi = i1; which = 1; }
        int bl = lane;
#pragma unroll
        for (int off = 16; off; off >>= 1) {
            float om = __shfl_xor_sync(0xffffffffu, bm, off);
            int   oi = __shfl_xor_sync(0xffffffffu, bi, off);
            int   ol = __shfl_xor_sync(0xffffffffu, bl, off);
            if (om < bm || (om == bm && ol < bl)) { bm = om; bi = oi; bl = ol; }
        }
        if (lane == 0) g_idx[gw * KNN + r] = bi;
        if (bl == lane) {
            if (which == 0) d0 = 3.4e38f; else d1 = 3.4e38f;
        }
    }
}

// ---------------------------------------------------------------------------
// Fused attention: 8 points/block (warp-per-point), mma logits (R13 config).
// ---------------------------------------------------------------------------
#define AT_W1L  20480
#define AT_WW2  40960
#define AT_SCR  45056
#define AT_T3   81920
#define AT_JS   83968
#define ATTN_SMEM_BYTES 84480

#define FMA8(hs, u, vv, off)                               \
    acc[(off)+0] = fmaf(hs, u.x,  acc[(off)+0]);           \
    acc[(off)+1] = fmaf(hs, u.y,  acc[(off)+1]);           \
    acc[(off)+2] = fmaf(hs, u.z,  acc[(off)+2]);           \
    acc[(off)+3] = fmaf(hs, u.w,  acc[(off)+3]);           \
    acc[(off)+4] = fmaf(hs, vv.x, acc[(off)+4]);           \
    acc[(off)+5] = fmaf(hs, vv.y, acc[(off)+5]);           \
    acc[(off)+6] = fmaf(hs, vv.z, acc[(off)+6]);           \
    acc[(off)+7] = fmaf(hs, vv.w, acc[(off)+7]);

__global__ __launch_bounds__(256, 2)
void attn_kernel(
    const float* __restrict__ xyz,
    const float* __restrict__ Wp1, const float* __restrict__ bp1,
    const float* __restrict__ gp,  const float* __restrict__ betap,
    const float* __restrict__ Wp2, const float* __restrict__ bp2,
    const float* __restrict__ gw1, const float* __restrict__ betaw1,
    const float* __restrict__ bw1,
    const float* __restrict__ gw2, const float* __restrict__ betaw2,
    const float* __restrict__ Ww2, const float* __restrict__ bw2,
    float* __restrict__ out)
{
    extern __shared__ __align__(16) char smx[];
    __nv_bfloat16* W1Hs = (__nv_bfloat16*)smx;
    __nv_bfloat16* W1Ls = (__nv_bfloat16*)(smx + AT_W1L);
    float* Ww2s = (float*)(smx + AT_WW2);
    float* T3s  = (float*)(smx + AT_T3);
    int*   Js   = (int*)(smx + AT_JS);

    const int t = threadIdx.x;

    for (int i2 = t; i2 < 1024; i2 += 256) {
        int row = i2 >> 2, q = i2 & 3;
        *(uint4*)((char*)W1Hs + row * 80 + q * 16) =
            *(const uint4*)(g_w1h + row * 32 + q * 8);
        *(uint4*)((char*)W1Ls + row * 80 + q * 16) =
            *(const uint4*)(g_w1l + row * 32 + q * 8);
    }
    *(float4*)&Ww2s[t * 4] = *(const float4*)&Ww2[t * 4];

    const int w    = t >> 5;
    const int lane = t & 31;
    const int P    = blockIdx.x * 8 + w;
    char* scr = smx + AT_SCR + w * 4608;
    __nv_bfloat16* Hh = (__nv_bfloat16*)scr;             // [16][72]
    __nv_bfloat16* Hl = (__nv_bfloat16*)(scr + 2304);    // [16][72]

    const float pix = xyz[P * 3 + 0];
    const float piy = xyz[P * 3 + 1];
    const float piz = xyz[P * 3 + 2];
    if (lane < KNN) {
        int j = g_idx[P * KNN + lane];
        Js[w * 16 + lane] = j;
        float dx = xyz[j * 3 + 0] - pix;
        float dy = xyz[j * 3 + 1] - piy;
        float dz = xyz[j * 3 + 2] - piz;
        float a0 = dx * Wp1[0] + dy * Wp1[3] + dz * Wp1[6] + bp1[0];
        float a1 = dx * Wp1[1] + dy * Wp1[4] + dz * Wp1[7] + bp1[1];
        float a2 = dx * Wp1[2] + dy * Wp1[5] + dz * Wp1[8] + bp1[2];
        T3s[(w * 16 + lane) * 4 + 0] = fmaxf(fmaf(gp[0], a0, betap[0]), 0.f);
        T3s[(w * 16 + lane) * 4 + 1] = fmaxf(fmaf(gp[1], a1, betap[1]), 0.f);
        T3s[(w * 16 + lane) * 4 + 2] = fmaxf(fmaf(gp[2], a2, betap[2]), 0.f);
    }
    __syncthreads();

    float W0p[8], W1p[8], W2p[8], C0p[8], g1p[8];
#pragma unroll
    for (int cc = 0; cc < 8; cc++) {
        int c = cc * 32 + lane;
        float g = gw1[c];
        g1p[cc] = g;
        W0p[cc] = g * Wp2[c];
        W1p[cc] = g * Wp2[256 + c];
        W2p[cc] = g * Wp2[512 + c];
        C0p[cc] = fmaf(g, bp2[c] - g_q[(size_t)P * CDIM + c], betaw1[c]);
    }

    float acc[16];
#pragma unroll
    for (int i = 0; i < 16; i++) acc[i] = 0.f;

#pragma unroll
    for (int ch = 0; ch < 4; ch++) {
#pragma unroll 4
        for (int k = 0; k < KNN; k++) {
            int j = Js[w * 16 + k];
            float t0 = T3s[(w * 16 + k) * 4 + 0];
            float t1 = T3s[(w * 16 + k) * 4 + 1];
            float t2 = T3s[(w * 16 + k) * 4 + 2];
            const float* krow = g_k + (size_t)j * CDIM + ch * 64;
#pragma unroll
            for (int cc = 0; cc < 2; cc++) {
                int a = ch * 2 + cc;
                float kv = krow[cc * 32 + lane];
                float pr = fmaf(t0, W0p[a], fmaf(t1, W1p[a], fmaf(t2, W2p[a], C0p[a])));
                float hv = fmaxf(fmaf(g1p[a], kv, pr), 0.f);
                __nv_bfloat16 hhv = __float2bfloat16(hv);
                Hh[k * 72 + cc * 32 + lane] = hhv;
                Hl[k * 72 + cc * 32 + lane] =
                    __float2bfloat16(hv - __bfloat162float(hhv));
            }
        }
        __syncwarp();

#pragma unroll
        for (int kt = 0; kt < 4; kt++) {
            unsigned int ah[4], al[4], bh[4][2], bl[4][2];
            {
                int row = lane & 15;
                int colb = (kt * 16 + ((lane >> 4) << 3)) * 2;
                ldsm4(&ah[0], s2u((char*)Hh + row * 144 + colb));
                ldsm4(&al[0], s2u((char*)Hl + row * 144 + colb));
            }
            int krg = ch * 64 + kt * 16 + (lane & 15);
#pragma unroll
            for (int np = 0; np < 2; np++) {
                int nc = np * 16 + ((lane >> 4) << 3);
                unsigned int r[4];
                ldsm4t(&r[0], s2u((char*)W1Hs + (krg * 40 + nc) * 2));
                bh[np * 2][0] = r[0]; bh[np * 2][1] = r[1];
                bh[np * 2 + 1][0] = r[2]; bh[np * 2 + 1][1] = r[3];
                ldsm4t(&r[0], s2u((char*)W1Ls + (krg * 40 + nc) * 2));
                bl[np * 2][0] = r[0]; bl[np * 2][1] = r[1];
                bl[np * 2 + 1][0] = r[2]; bl[np * 2 + 1][1] = r[3];
            }
#pragma unroll
            for (int nt = 0; nt < 4; nt++) {
                mma_bf16(acc + nt * 4, &ah[0], &bh[nt][0]);
                mma_bf16(acc + nt * 4, &ah[0], &bl[nt][0]);
                mma_bf16(acc + nt * 4, &al[0], &bh[nt][0]);
            }
        }
        __syncwarp();
    }

    float* H2W = (float*)scr;
    {
        const int r0 = lane >> 2;
        const int cpair = (lane & 3) * 2;
#pragma unroll
        for (int nt = 0; nt < 4; nt++) {
            int cs = nt * 8 + cpair;
            float b0 = bw1[cs], b1 = bw1[cs + 1];
            float ga = gw2[cs], gb = gw2[cs + 1];
            float ba = betaw2[cs], bb = betaw2[cs + 1];
            float a00 = fmaxf(fmaf(ga, acc[nt * 4 + 0] + b0, ba), 0.f);
            float a01 = fmaxf(fmaf(gb, acc[nt * 4 + 1] + b1, bb), 0.f);
            float a10 = fmaxf(fmaf(ga, acc[nt * 4 + 2] + b0, ba), 0.f);
            float a11 = fmaxf(fmaf(gb, acc[nt * 4 + 3] + b1, bb), 0.f);
            *(float2*)&H2W[r0 * 36 + cs]       = make_float2(a00, a01);
            *(float2*)&H2W[(r0 + 8) * 36 + cs] = make_float2(a10, a11);
        }
    }
    __syncwarp();

    const int k0  = lane & 7;
    const int k1  = k0 + 8;
    const int cso = (lane >> 3) << 3;

#pragma unroll
    for (int i = 0; i < 16; i++) acc[i] = 0.f;
    {
        const float* x0p = H2W + k0 * 36;
        const float* x1p = H2W + k1 * 36;
#pragma unroll
        for (int cp = 0; cp < 32; cp += 4) {
            float4 ha = *(const float4*)(x0p + cp);
            float4 hb = *(const float4*)(x1p + cp);
            const float* wr = Ww2s + cp * 32 + cso;
            { const float4 u = *(const float4*)(wr); const float4 vv = *(const float4*)(wr + 4);
              FMA8(ha.x, u, vv, 0) FMA8(hb.x, u, vv, 8) }
            wr += 32;
            { const float4 u = *(const float4*)(wr); const float4 vv = *(const float4*)(wr + 4);
              FMA8(ha.y, u, vv, 0) FMA8(hb.y, u, vv, 8) }
            wr += 32;
            { const float4 u = *(const float4*)(wr); const float4 vv = *(const float4*)(wr + 4);
              FMA8(ha.z, u, vv, 0) FMA8(hb.z, u, vv, 8) }
            wr += 32;
            { const float4 u = *(const float4*)(wr); const float4 vv = *(const float4*)(wr + 4);
              FMA8(ha.w, u, vv, 0) FMA8(hb.w, u, vv, 8) }
        }
    }
    __syncwarp();

    float* WgW = (float*)scr;
    {
        float wa[8], wb[8];
#pragma unroll
        for (int i = 0; i < 8; i++) {
            int cs = cso + i;
            float la = acc[i]     + bw2[cs];
            float lb = acc[8 + i] + bw2[cs];
            float m = fmaxf(la, lb);
            m = fmaxf(m, __shfl_xor_sync(0xffffffffu, m, 1));
            m = fmaxf(m, __shfl_xor_sync(0xffffffffu, m, 2));
            m = fmaxf(m, __shfl_xor_sync(0xffffffffu, m, 4));
            float ea = __expf(la - m);
            float eb = __expf(lb - m);
            float s = ea + eb;
            s += __shfl_xor_sync(0xffffffffu, s, 1);
            s += __shfl_xor_sync(0xffffffffu, s, 2);
            s += __shfl_xor_sync(0xffffffffu, s, 4);
            float inv = 1.f / s;
            wa[i] = ea * inv;
            wb[i] = eb * inv;
        }
#pragma unroll
        for (int i = 0; i < 8; i++) {
            WgW[(cso + i) * 20 + k0] = wa[i];
            WgW[(cso + i) * 20 + k1] = wb[i];
        }
    }
    __syncwarp();

    float wk[16];
    {
        const float* wp = WgW + lane * 20;
        *(float4*)&wk[0]  = *(const float4*)(wp);
        *(float4*)&wk[4]  = *(const float4*)(wp + 4);
        *(float4*)&wk[8]  = *(const float4*)(wp + 8);
        *(float4*)&wk[12] = *(const float4*)(wp + 12);
    }

    float W0o[8], W1o[8], W2o[8], bpo[8], acc3[8];
#pragma unroll
    for (int cc = 0; cc < 8; cc++) {
        int c = cc * 32 + lane;
        W0o[cc] = Wp2[c];
        W1o[cc] = Wp2[256 + c];
        W2o[cc] = Wp2[512 + c];
        bpo[cc] = bp2[c];
        acc3[cc] = g_x[(size_t)P * CDIM + c];
    }

#pragma unroll 4
    for (int k = 0; k < KNN; k++) {
        int j = Js[w * 16 + k];
        float t0 = T3s[(w * 16 + k) * 4 + 0];
        float t1 = T3s[(w * 16 + k) * 4 + 1];
        float t2 = T3s[(w * 16 + k) * 4 + 2];
        const float* vrow = g_v + (size_t)j * CDIM;
        float wgt = wk[k];
#pragma unroll
        for (int cc = 0; cc < 8; cc++) {
            int c = cc * 32 + lane;
            float pr = fmaf(t0, W0o[cc], fmaf(t1, W1o[cc], fmaf(t2, W2o[cc], bpo[cc])));
            acc3[cc] = fmaf(vrow[c] + pr, wgt, acc3[cc]);
        }
    }

#pragma unroll
    for (int cc = 0; cc < 8; cc++)
        out[(size_t)P * CDIM + cc * 32 + lane] = acc3[cc];
}

// ---------------------------------------------------------------------------
// Launch — fork-join: kNN branch runs concurrently with embed/conv/qkv chain.
// Streams/events created lazily on the first (uncaptured) call; the captured
// graph and launched work are identical on every call.
// ---------------------------------------------------------------------------
extern "C" void kernel_launch(void* const* d_in, const int* in_sizes, int n_in,
                              void* d_out, int out_size)
{
    const float* x_main = (const float*)d_in[0];
    const float* x_mod  = (const float*)d_in[1];
    const float* xyz    = (const float*)d_in[2];
    const float* We2d   = (const float*)d_in[3];
    const float* be2d   = (const float*)d_in[4];
    const float* We3d   = (const float*)d_in[5];
    const float* be3d   = (const float*)d_in[6];
    const float* Wq     = (const float*)d_in[7];
    const float* bq     = (const float*)d_in[8];
    const float* Wk     = (const float*)d_in[9];
    const float* bk     = (const float*)d_in[10];
    const float* Wv     = (const float*)d_in[11];
    const float* bv     = (const float*)d_in[12];
    const float* Wp1    = (const float*)d_in[13];
    const float* bp1    = (const float*)d_in[14];
    const float* gp     = (const float*)d_in[15];
    const float* betap  = (const float*)d_in[16];
    const float* Wp2    = (const float*)d_in[17];
    const float* bp2    = (const float*)d_in[18];
    const float* gw1    = (const float*)d_in[19];
    const float* betaw1 = (const float*)d_in[20];
    const float* Ww1    = (const float*)d_in[21];
    const float* bw1    = (const float*)d_in[22];
    const float* gw2    = (const float*)d_in[23];
    const float* betaw2 = (const float*)d_in[24];
    const float* Ww2    = (const float*)d_in[25];
    const float* bw2    = (const float*)d_in[26];
    float* out = (float*)d_out;

    float *dx, *dq, *dk, *dv;
    cudaGetSymbolAddress((void**)&dx, g_x);
    cudaGetSymbolAddress((void**)&dq, g_q);
    cudaGetSymbolAddress((void**)&dk, g_k);
    cudaGetSymbolAddress((void**)&dv, g_v);

    cudaFuncSetAttribute(qkv_mma_kernel, cudaFuncAttributeMaxDynamicSharedMemorySize,
                         QKV_SMEM_BYTES);
    cudaFuncSetAttribute(attn_kernel, cudaFuncAttributeMaxDynamicSharedMemorySize,
                         ATTN_SMEM_BYTES);
    cudaFuncSetAttribute(knn_kernel, cudaFuncAttributeMaxDynamicSharedMemorySize,
                         KNN_SMEM_BYTES);

    // Lazy one-time stream/event setup (first call is the uncaptured
    // correctness run, so creation never happens during graph capture).
    static cudaStream_t sB = nullptr;
    static cudaEvent_t  evFork = nullptr, evJoin = nullptr;
    if (sB == nullptr) {
        cudaStreamCreateWithFlags(&sB, cudaStreamNonBlocking);
        cudaEventCreateWithFlags(&evFork, cudaEventDisableTiming);
        cudaEventCreateWithFlags(&evJoin, cudaEventDisableTiming);
    }

    // Fork: branch B (kNN chain, needs only xyz) runs concurrently with
    // the embed -> convert -> qkv chain on the main stream.
    cudaEventRecord(evFork, 0);
    cudaStreamWaitEvent(sB, evFork, 0);

    // Branch B: kNN partials + merge
    knn_kernel<<<dim3(NPTS / 128, NPART), 128, KNN_SMEM_BYTES, sB>>>(xyz);
    knn_merge_kernel<<<NPTS * 32 / 256, 256, 0, sB>>>();
    cudaEventRecord(evJoin, sB);

    // Main stream: embed (+ fused bf16 conversion), weight conversions, qkv
    sgemm_embed_kernel<<<dim3(NPTS / 128, 1), 256>>>(x_main, We3d, be3d, dx, 0);
    sgemm_embed_kernel<<<dim3(NPTS / 128, 1), 256>>>(x_mod,  We2d, be2d, dx, 128);
    convert_w_kernel<<<CDIM * 768 / 256, 256>>>(Wq, Wk, Wv);
    convert_w1_kernel<<<CDIM * 32 / 256, 256>>>(Ww1);
    qkv_mma_kernel<<<dim3(NPTS / 128, 6), 256, QKV_SMEM_BYTES>>>(bq, bk, bv, dq, dk, dv);

    // Join: attn needs both branches
    cudaStreamWaitEvent(0, evJoin, 0);

    attn_kernel<<<NPTS / 8, 256, ATTN_SMEM_BYTES>>>(
        xyz, Wp1, bp1, gp, betap, Wp2, bp2, gw1, betaw1,
        bw1, gw2, betaw2, Ww2, bw2, out);
}

// round 17
// speedup vs baseline: 1.1144x; 1.0014x over previous
#include <cuda_runtime.h>
#include <cuda_bf16.h>
#include <cstdint>
#include <math.h>

// ---------------------------------------------------------------------------
// Problem constants
// ---------------------------------------------------------------------------
#define NPTS   16384     // B*N
#define NSAMP  8192      // points per sample
#define CDIM   256
#define KNN    16
#define NPART  4
#define PARTLEN (NSAMP / NPART)   // 2048
#define RMAX   16        // kNN ring capacity

// kNN dynamic smem layout (bytes)
#define KS_TILE 0
#define KS_HD   2048
#define KS_HI   10240
#define KS_RD   18432
#define KS_RI   26624
#define KNN_SMEM_BYTES 34816

// ---------------------------------------------------------------------------
// Scratch (static __device__ — no allocation allowed)
// ---------------------------------------------------------------------------
__device__ float g_x[NPTS * CDIM];
__device__ float g_q[NPTS * CDIM];
__device__ float g_k[NPTS * CDIM];
__device__ float g_v[NPTS * CDIM];
__device__ float g_cd[NPTS * NPART * KNN];
__device__ int   g_ci[NPTS * NPART * KNN];
__device__ int   g_idx[NPTS * KNN];
__device__ __align__(16) __nv_bfloat16 g_xh[NPTS * CDIM];
__device__ __align__(16) __nv_bfloat16 g_xl[NPTS * CDIM];
__device__ __align__(16) __nv_bfloat16 g_wh[CDIM * 768];
__device__ __align__(16) __nv_bfloat16 g_wl[CDIM * 768];
__device__ __align__(16) __nv_bfloat16 g_w1h[CDIM * 32];
__device__ __align__(16) __nv_bfloat16 g_w1l[CDIM * 32];

// ---------------------------------------------------------------------------
// mma.sync + cp.async helpers
// ---------------------------------------------------------------------------
__device__ __forceinline__ unsigned int s2u(const void* p) {
    return (unsigned int)__cvta_generic_to_shared(p);
}
__device__ __forceinline__ void ldsm4(unsigned int* r, unsigned int a) {
    asm volatile("ldmatrix.sync.aligned.m8n8.x4.shared.b16 {%0,%1,%2,%3},[%4];"
        : "=r"(r[0]), "=r"(r[1]), "=r"(r[2]), "=r"(r[3]) : "r"(a));
}
__device__ __forceinline__ void ldsm4t(unsigned int* r, unsigned int a) {
    asm volatile("ldmatrix.sync.aligned.m8n8.x4.trans.shared.b16 {%0,%1,%2,%3},[%4];"
        : "=r"(r[0]), "=r"(r[1]), "=r"(r[2]), "=r"(r[3]) : "r"(a));
}
__device__ __forceinline__ void mma_bf16(float* c, const unsigned int* a,
                                         const unsigned int* b) {
    asm volatile("mma.sync.aligned.m16n8k16.row.col.f32.bf16.bf16.f32 "
        "{%0,%1,%2,%3},{%4,%5,%6,%7},{%8,%9},{%0,%1,%2,%3};"
        : "+f"(c[0]), "+f"(c[1]), "+f"(c[2]), "+f"(c[3])
        : "r"(a[0]), "r"(a[1]), "r"(a[2]), "r"(a[3]), "r"(b[0]), "r"(b[1]));
}
#define CP_ASYNC16(dst, src) \
    asm volatile("cp.async.cg.shared.global [%0],[%1],16;" :: "r"(dst), "l"(src))
#define CP_COMMIT() asm volatile("cp.async.commit_group;")
#define CP_WAIT(n)  asm volatile("cp.async.wait_group %0;" :: "n"(n))

// ---------------------------------------------------------------------------
// Weight bf16 hi/lo conversions
// ---------------------------------------------------------------------------
__global__ __launch_bounds__(256)
void convert_w_kernel(const float* __restrict__ Wq, const float* __restrict__ Wk,
                      const float* __restrict__ Wv)
{
    const int gid = blockIdx.x * 256 + threadIdx.x;
    const int k    = gid / 768;
    const int ncat = gid % 768;
    const int z = ncat >> 8;
    const int n = ncat & 255;
    const float* W = (z == 0) ? Wq : (z == 1) ? Wk : Wv;
    float v = W[k * 256 + n];
    __nv_bfloat16 hi = __float2bfloat16(v);
    __nv_bfloat16 lo = __float2bfloat16(v - __bfloat162float(hi));
    g_wh[k * 768 + ncat] = hi;
    g_wl[k * 768 + ncat] = lo;
}

__global__ __launch_bounds__(256)
void convert_w1_kernel(const float* __restrict__ Ww1)
{
    const int gid = blockIdx.x * 256 + threadIdx.x;   // 8192
    float v = Ww1[gid];
    __nv_bfloat16 hi = __float2bfloat16(v);
    g_w1h[gid] = hi;
    g_w1l[gid] = __float2bfloat16(v - __bfloat162float(hi));
}

// ---------------------------------------------------------------------------
// QKV tensor-core GEMM, bf16 hi/lo, 2-stage cp.async pipeline.
// ---------------------------------------------------------------------------
#define A_STRIDE 40
#define B_STRIDE 136
#define ST_AH 0
#define ST_AL 5120
#define ST_BH 10240
#define ST_BL 14592
#define ST_TOTAL 18944
#define QKV_SMEM_BYTES (2 * ST_TOTAL * 2)

__global__ __launch_bounds__(256)
void qkv_mma_kernel(const float* __restrict__ bq, const float* __restrict__ bk,
                    const float* __restrict__ bv,
                    float* __restrict__ Cq, float* __restrict__ Ck,
                    float* __restrict__ Cv)
{
    extern __shared__ __align__(16) __nv_bfloat16 qsm[];

    const int t    = threadIdx.x;
    const int lane = t & 31;
    const int warp = t >> 5;
    const int wm   = warp & 1;
    const int wn   = warp >> 1;
    const int m0   = blockIdx.x * 128;
    const int n0g  = blockIdx.y * 128;

    float acc[4][4][4];
#pragma unroll
    for (int i = 0; i < 4; i++)
#pragma unroll
        for (int j = 0; j < 4; j++)
#pragma unroll
            for (int l = 0; l < 4; l++) acc[i][j][l] = 0.f;

    auto issue_stage = [&](int it, int b) {
        const int k0 = it * 32;
        __nv_bfloat16* Ah = qsm + b * ST_TOTAL + ST_AH;
        __nv_bfloat16* Al = qsm + b * ST_TOTAL + ST_AL;
        __nv_bfloat16* Bh = qsm + b * ST_TOTAL + ST_BH;
        __nv_bfloat16* Bl = qsm + b * ST_TOTAL + ST_BL;
#pragma unroll
        for (int rep = 0; rep < 2; rep++) {
            int id = t + rep * 256;
            int arr = id >> 2, acc_ = id & 3;
            CP_ASYNC16(s2u(Ah + arr * A_STRIDE + acc_ * 8),
                       g_xh + (size_t)(m0 + arr) * 256 + k0 + acc_ * 8);
            CP_ASYNC16(s2u(Al + arr * A_STRIDE + acc_ * 8),
                       g_xl + (size_t)(m0 + arr) * 256 + k0 + acc_ * 8);
            int br = id >> 4, bc = id & 15;
            CP_ASYNC16(s2u(Bh + br * B_STRIDE + bc * 8),
                       g_wh + (size_t)(k0 + br) * 768 + n0g + bc * 8);
            CP_ASYNC16(s2u(Bl + br * B_STRIDE + bc * 8),
                       g_wl + (size_t)(k0 + br) * 768 + n0g + bc * 8);
        }
        CP_COMMIT();
    };

    issue_stage(0, 0);

#pragma unroll
    for (int it = 0; it < 8; it++) {
        const int b = it & 1;
        if (it + 1 < 8) { issue_stage(it + 1, b ^ 1); CP_WAIT(1); }
        else            { CP_WAIT(0); }
        __syncthreads();

        const __nv_bfloat16* Ah = qsm + b * ST_TOTAL + ST_AH;
        const __nv_bfloat16* Al = qsm + b * ST_TOTAL + ST_AL;
        const __nv_bfloat16* Bh = qsm + b * ST_TOTAL + ST_BH;
        const __nv_bfloat16* Bl = qsm + b * ST_TOTAL + ST_BL;

#pragma unroll
        for (int ks = 0; ks < 2; ks++) {
            unsigned int ah[4][4], al[4][4], bh[4][2], bl[4][2];
#pragma unroll
            for (int mm = 0; mm < 4; mm++) {
                int row = wm * 64 + mm * 16 + (lane & 15);
                int col = ks * 16 + (lane >> 4) * 8;
                ldsm4(&ah[mm][0], s2u(Ah + row * A_STRIDE + col));
                ldsm4(&al[mm][0], s2u(Al + row * A_STRIDE + col));
            }
#pragma unroll
            for (int nb = 0; nb < 2; nb++) {
                int kk = ks * 16 + (lane & 15);
                int nc = wn * 32 + nb * 16 + (lane >> 4) * 8;
                unsigned int r[4];
                ldsm4t(&r[0], s2u(Bh + kk * B_STRIDE + nc));
                bh[nb * 2][0] = r[0]; bh[nb * 2][1] = r[1];
                bh[nb * 2 + 1][0] = r[2]; bh[nb * 2 + 1][1] = r[3];
                ldsm4t(&r[0], s2u(Bl + kk * B_STRIDE + nc));
                bl[nb * 2][0] = r[0]; bl[nb * 2][1] = r[1];
                bl[nb * 2 + 1][0] = r[2]; bl[nb * 2 + 1][1] = r[3];
            }
#pragma unroll
            for (int mm = 0; mm < 4; mm++)
#pragma unroll
                for (int nn = 0; nn < 4; nn++) {
                    mma_bf16(&acc[mm][nn][0], &ah[mm][0], &bh[nn][0]);
                    mma_bf16(&acc[mm][nn][0], &ah[mm][0], &bl[nn][0]);
                    mma_bf16(&acc[mm][nn][0], &al[mm][0], &bh[nn][0]);
                }
        }
        __syncthreads();
    }

    const int z = n0g >> 8;
    const float* bias = (z == 0) ? bq : (z == 1) ? bk : bv;
    float* C          = (z == 0) ? Cq : (z == 1) ? Ck : Cv;
    const int ncol0 = n0g & 255;

#pragma unroll
    for (int mm = 0; mm < 4; mm++) {
#pragma unroll
        for (int nn = 0; nn < 4; nn++) {
            int rowg = m0 + wm * 64 + mm * 16 + (lane >> 2);
            int col  = ncol0 + wn * 32 + nn * 8 + (lane & 3) * 2;
            float b0 = bias[col], b1 = bias[col + 1];
            float2 v0 = make_float2(acc[mm][nn][0] + b0, acc[mm][nn][1] + b1);
            float2 v1 = make_float2(acc[mm][nn][2] + b0, acc[mm][nn][3] + b1);
            *(float2*)&C[(size_t)rowg * 256 + col]       = v0;
            *(float2*)&C[(size_t)(rowg + 8) * 256 + col] = v1;
        }
    }
}

// ---------------------------------------------------------------------------
// Embed SGEMM (both halves in one launch: blockIdx.y = 0 -> x_main/We3d,
// blockIdx.y = 1 -> x_mod/We2d) with fused bf16 hi/lo epilogue.
// ---------------------------------------------------------------------------
__global__ __launch_bounds__(256, 2)
void sgemm_embed_kernel(const float* __restrict__ A0, const float* __restrict__ W0,
                        const float* __restrict__ bias0,
                        const float* __restrict__ A1, const float* __restrict__ W1,
                        const float* __restrict__ bias1,
                        float* __restrict__ C)
{
    const int KD = 128, NW = 128;
    __shared__ float As[8 * 128];
    __shared__ float Bs[8 * 132];

    const int t  = threadIdx.x;
    const int bm = blockIdx.x * 128;
    const int half = blockIdx.y;
    const float* A    = half ? A1 : A0;
    const float* W    = half ? W1 : W0;
    const float* bias = half ? bias1 : bias0;
    const int coff = half * 128;

    const int arow = t >> 1;
    const int ak   = (t & 1) * 4;
    const int wkk  = t >> 5;
    const int wn   = (t & 31) * 4;
    const int ty = t >> 4;
    const int tx = t & 15;

    float acc[8][8];
#pragma unroll
    for (int i = 0; i < 8; i++)
#pragma unroll
        for (int j = 0; j < 8; j++) acc[i][j] = 0.f;

    const float* Aptr = A + (size_t)(bm + arow) * KD + ak;
    const float* Wptr = W + (size_t)wkk * NW + wn;

    float4 av = *(const float4*)Aptr;
    float4 wv = *(const float4*)Wptr;

    for (int k0 = 0; k0 < KD; k0 += 8) {
        As[(ak + 0) * 128 + arow] = av.x;
        As[(ak + 1) * 128 + arow] = av.y;
        As[(ak + 2) * 128 + arow] = av.z;
        As[(ak + 3) * 128 + arow] = av.w;
        *(float4*)&Bs[wkk * 132 + wn] = wv;
        __syncthreads();
        if (k0 + 8 < KD) {
            av = *(const float4*)(Aptr + k0 + 8);
            wv = *(const float4*)(Wptr + (size_t)(k0 + 8) * NW);
        }
#pragma unroll
        for (int kk = 0; kk < 8; kk++) {
            float4 a0 = *(const float4*)&As[kk * 128 + ty * 8];
            float4 a1 = *(const float4*)&As[kk * 128 + ty * 8 + 4];
            float4 b0 = *(const float4*)&Bs[kk * 132 + tx * 8];
            float4 b1 = *(const float4*)&Bs[kk * 132 + tx * 8 + 4];
            float ar[8] = {a0.x, a0.y, a0.z, a0.w, a1.x, a1.y, a1.z, a1.w};
            float br[8] = {b0.x, b0.y, b0.z, b0.w, b1.x, b1.y, b1.z, b1.w};
#pragma unroll
            for (int i = 0; i < 8; i++)
#pragma unroll
                for (int j = 0; j < 8; j++)
                    acc[i][j] = fmaf(ar[i], br[j], acc[i][j]);
        }
        __syncthreads();
    }

#pragma unroll
    for (int i = 0; i < 8; i++) {
        const size_t row = (size_t)(bm + ty * 8 + i);
        float* crow = C + row * CDIM + coff + tx * 8;
        float o[8];
#pragma unroll
        for (int j = 0; j < 8; j++) o[j] = acc[i][j] + bias[tx * 8 + j];
        *(float4*)(crow)     = make_float4(o[0], o[1], o[2], o[3]);
        *(float4*)(crow + 4) = make_float4(o[4], o[5], o[6], o[7]);
        __nv_bfloat16 h[8], l[8];
#pragma unroll
        for (int j = 0; j < 8; j++) {
            h[j] = __float2bfloat16(o[j]);
            l[j] = __float2bfloat16(o[j] - __bfloat162float(h[j]));
        }
        *(uint4*)&g_xh[row * CDIM + coff + tx * 8] = *(const uint4*)&h[0];
        *(uint4*)&g_xl[row * CDIM + coff + tx * 8] = *(const uint4*)&l[0];
    }
}

// ---------------------------------------------------------------------------
// kNN partial top-16 (R13 measured-best config: NPART=4, dynamic smem).
// ---------------------------------------------------------------------------
__global__ __launch_bounds__(128)
void knn_kernel(const float* __restrict__ xyz)
{
    extern __shared__ __align__(16) char ksm[];
    float4* tile = (float4*)(ksm + KS_TILE);
    float*  hd   = (float*)(ksm + KS_HD);
    int*    hi   = (int*)(ksm + KS_HI);
    float*  rdq  = (float*)(ksm + KS_RD);
    int*    riq  = (int*)(ksm + KS_RI);

    const int t = threadIdx.x;
    const int i = blockIdx.x * 128 + t;

    const float m2x = -2.f * xyz[i * 3 + 0];
    const float m2y = -2.f * xyz[i * 3 + 1];
    const float m2z = -2.f * xyz[i * 3 + 2];

    const int base   = (i >> 13) << 13;
    const int jstart = base + blockIdx.y * PARTLEN;

    {
        int jg = jstart + t;
        float x = xyz[jg * 3 + 0];
        float y = xyz[jg * 3 + 1];
        float z = xyz[jg * 3 + 2];
        tile[t] = make_float4(x, y, z, x * x + y * y + z * z);
    }
    __syncthreads();

    float worst = -1e30f;
    int   ws = 0, cnt = 0;

#pragma unroll
    for (int s = 0; s < KNN; s++) {
        float4 f = tile[s];
        float d = fmaf(m2x, f.x, fmaf(m2y, f.y, fmaf(m2z, f.z, f.w)));
        hd[s * 128 + t] = d;
        hi[s * 128 + t] = jstart + s;
        if (d > worst) { worst = d; ws = s; }
    }

    auto consolidate = [&]() {
        for (int e = 0; e < cnt; e++) {
            float d = rdq[e * 128 + t];
            if (d < worst) {
                hd[ws * 128 + t] = d;
                hi[ws * 128 + t] = riq[e * 128 + t];
                worst = -1e30f;
#pragma unroll
                for (int s = 0; s < KNN; s++) {
                    float v = hd[s * 128 + t];
                    if (v > worst) { worst = v; ws = s; }
                }
            }
        }
        cnt = 0;
    };

    for (int jj = KNN; jj < 128; jj += 8) {
#pragma unroll
        for (int u = 0; u < 8; u++) {
            float4 f = tile[jj + u];
            float d = fmaf(m2x, f.x, fmaf(m2y, f.y, fmaf(m2z, f.z, f.w)));
            if (d < worst) {
                rdq[cnt * 128 + t] = d;
                riq[cnt * 128 + t] = jstart + jj + u;
                cnt++;
            }
        }
        if (__any_sync(0xffffffffu, cnt >= RMAX - 8)) consolidate();
    }

    for (int t0 = 128; t0 < PARTLEN; t0 += 128) {
        __syncthreads();
        {
            int jg = jstart + t0 + t;
            float x = xyz[jg * 3 + 0];
            float y = xyz[jg * 3 + 1];
            float z = xyz[jg * 3 + 2];
            tile[t] = make_float4(x, y, z, x * x + y * y + z * z);
        }
        __syncthreads();
        for (int jj = 0; jj < 128; jj += 8) {
#pragma unroll
            for (int u = 0; u < 8; u++) {
                float4 f = tile[jj + u];
                float d = fmaf(m2x, f.x, fmaf(m2y, f.y, fmaf(m2z, f.z, f.w)));
                if (d < worst) {
                    rdq[cnt * 128 + t] = d;
                    riq[cnt * 128 + t] = jstart + t0 + jj + u;
                    cnt++;
                }
            }
            if (__any_sync(0xffffffffu, cnt >= RMAX - 8)) consolidate();
        }
    }
    consolidate();

    const int ob = i * (NPART * KNN) + blockIdx.y * KNN;
#pragma unroll
    for (int s = 0; s < KNN; s++) {
        g_cd[ob + s] = hd[s * 128 + t];
        g_ci[ob + s] = hi[s * 128 + t];
    }
}

// ---------------------------------------------------------------------------
// kNN merge: one warp per point, 64 candidates (2/lane), shfl extract-min.
// ---------------------------------------------------------------------------
__global__ __launch_bounds__(256)
void knn_merge_kernel()
{
    const int gw   = (blockIdx.x * 256 + threadIdx.x) >> 5;
    const int lane = threadIdx.x & 31;

    float d0 = g_cd[gw * 64 + lane];
    float d1 = g_cd[gw * 64 + lane + 32];
    int   i0 = g_ci[gw * 64 + lane];
    int   i1 = g_ci[gw * 64 + lane + 32];

#pragma unroll
    for (int r = 0; r < KNN; r++) {
        int   which;
        float bm; int bi;
        if (d0 <= d1) { bm = d0; bi = i0; which = 0; }
        else          { bm = d1; bi = i1; which = 1; }
        int bl = lane;
#pragma unroll
        for (int off = 16; off; off >>= 1) {
            float om = __shfl_xor_sync(0xffffffffu, bm, off);
            int   oi = __shfl_xor_sync(0xffffffffu, bi, off);
            int   ol = __shfl_xor_sync(0xffffffffu, bl, off);
            if (om < bm || (om == bm && ol < bl)) { bm = om; bi = oi; bl = ol; }
        }
        if (lane == 0) g_idx[gw * KNN + r] = bi;
        if (bl == lane) {
            if (which == 0) d0 = 3.4e38f; else d1 = 3.4e38f;
        }
    }
}

// ---------------------------------------------------------------------------
// Fused attention: 8 points/block (warp-per-point), mma logits (R13 config).
// ---------------------------------------------------------------------------
#define AT_W1L  20480
#define AT_WW2  40960
#define AT_SCR  45056
#define AT_T3   81920
#define AT_JS   83968
#define ATTN_SMEM_BYTES 84480

#define FMA8(hs, u, vv, off)                               \
    acc[(off)+0] = fmaf(hs, u.x,  acc[(off)+0]);           \
    acc[(off)+1] = fmaf(hs, u.y,  acc[(off)+1]);           \
    acc[(off)+2] = fmaf(hs, u.z,  acc[(off)+2]);           \
    acc[(off)+3] = fmaf(hs, u.w,  acc[(off)+3]);           \
    acc[(off)+4] = fmaf(hs, vv.x, acc[(off)+4]);           \
    acc[(off)+5] = fmaf(hs, vv.y, acc[(off)+5]);           \
    acc[(off)+6] = fmaf(hs, vv.z, acc[(off)+6]);           \
    acc[(off)+7] = fmaf(hs, vv.w, acc[(off)+7]);

__global__ __launch_bounds__(256, 2)
void attn_kernel(
    const float* __restrict__ xyz,
    const float* __restrict__ Wp1, const float* __restrict__ bp1,
    const float* __restrict__ gp,  const float* __restrict__ betap,
    const float* __restrict__ Wp2, const float* __restrict__ bp2,
    const float* __restrict__ gw1, const float* __restrict__ betaw1,
    const float* __restrict__ bw1,
    const float* __restrict__ gw2, const float* __restrict__ betaw2,
    const float* __restrict__ Ww2, const float* __restrict__ bw2,
    float* __restrict__ out)
{
    extern __shared__ __align__(16) char smx[];
    __nv_bfloat16* W1Hs = (__nv_bfloat16*)smx;
    __nv_bfloat16* W1Ls = (__nv_bfloat16*)(smx + AT_W1L);
    float* Ww2s = (float*)(smx + AT_WW2);
    float* T3s  = (float*)(smx + AT_T3);
    int*   Js   = (int*)(smx + AT_JS);

    const int t = threadIdx.x;

    for (int i2 = t; i2 < 1024; i2 += 256) {
        int row = i2 >> 2, q = i2 & 3;
        *(uint4*)((char*)W1Hs + row * 80 + q * 16) =
            *(const uint4*)(g_w1h + row * 32 + q * 8);
        *(uint4*)((char*)W1Ls + row * 80 + q * 16) =
            *(const uint4*)(g_w1l + row * 32 + q * 8);
    }
    *(float4*)&Ww2s[t * 4] = *(const float4*)&Ww2[t * 4];

    const int w    = t >> 5;
    const int lane = t & 31;
    const int P    = blockIdx.x * 8 + w;
    char* scr = smx + AT_SCR + w * 4608;
    __nv_bfloat16* Hh = (__nv_bfloat16*)scr;             // [16][72]
    __nv_bfloat16* Hl = (__nv_bfloat16*)(scr + 2304);    // [16][72]

    const float pix = xyz[P * 3 + 0];
    const float piy = xyz[P * 3 + 1];
    const float piz = xyz[P * 3 + 2];
    if (lane < KNN) {
        int j = g_idx[P * KNN + lane];
        Js[w * 16 + lane] = j;
        float dx = xyz[j * 3 + 0] - pix;
        float dy = xyz[j * 3 + 1] - piy;
        float dz = xyz[j * 3 + 2] - piz;
        float a0 = dx * Wp1[0] + dy * Wp1[3] + dz * Wp1[6] + bp1[0];
        float a1 = dx * Wp1[1] + dy * Wp1[4] + dz * Wp1[7] + bp1[1];
        float a2 = dx * Wp1[2] + dy * Wp1[5] + dz * Wp1[8] + bp1[2];
        T3s[(w * 16 + lane) * 4 + 0] = fmaxf(fmaf(gp[0], a0, betap[0]), 0.f);
        T3s[(w * 16 + lane) * 4 + 1] = fmaxf(fmaf(gp[1], a1, betap[1]), 0.f);
        T3s[(w * 16 + lane) * 4 + 2] = fmaxf(fmaf(gp[2], a2, betap[2]), 0.f);
    }
    __syncthreads();

    float W0p[8], W1p[8], W2p[8], C0p[8], g1p[8];
#pragma unroll
    for (int cc = 0; cc < 8; cc++) {
        int c = cc * 32 + lane;
        float g = gw1[c];
        g1p[cc] = g;
        W0p[cc] = g * Wp2[c];
        W1p[cc] = g * Wp2[256 + c];
        W2p[cc] = g * Wp2[512 + c];
        C0p[cc] = fmaf(g, bp2[c] - g_q[(size_t)P * CDIM + c], betaw1[c]);
    }

    float acc[16];
#pragma unroll
    for (int i = 0; i < 16; i++) acc[i] = 0.f;

#pragma unroll
    for (int ch = 0; ch < 4; ch++) {
#pragma unroll 4
        for (int k = 0; k < KNN; k++) {
            int j = Js[w * 16 + k];
            float t0 = T3s[(w * 16 + k) * 4 + 0];
            float t1 = T3s[(w * 16 + k) * 4 + 1];
            float t2 = T3s[(w * 16 + k) * 4 + 2];
            const float* krow = g_k + (size_t)j * CDIM + ch * 64;
#pragma unroll
            for (int cc = 0; cc < 2; cc++) {
                int a = ch * 2 + cc;
                float kv = krow[cc * 32 + lane];
                float pr = fmaf(t0, W0p[a], fmaf(t1, W1p[a], fmaf(t2, W2p[a], C0p[a])));
                float hv = fmaxf(fmaf(g1p[a], kv, pr), 0.f);
                __nv_bfloat16 hhv = __float2bfloat16(hv);
                Hh[k * 72 + cc * 32 + lane] = hhv;
                Hl[k * 72 + cc * 32 + lane] =
                    __float2bfloat16(hv - __bfloat162float(hhv));
            }
        }
        __syncwarp();

#pragma unroll
        for (int kt = 0; kt < 4; kt++) {
            unsigned int ah[4], al[4], bh[4][2], bl[4][2];
            {
                int row = lane & 15;
                int colb = (kt * 16 + ((lane >> 4) << 3)) * 2;
                ldsm4(&ah[0], s2u((char*)Hh + row * 144 + colb));
                ldsm4(&al[0], s2u((char*)Hl + row * 144 + colb));
            }
            int krg = ch * 64 + kt * 16 + (lane & 15);
#pragma unroll
            for (int np = 0; np < 2; np++) {
                int nc = np * 16 + ((lane >> 4) << 3);
                unsigned int r[4];
                ldsm4t(&r[0], s2u((char*)W1Hs + (krg * 40 + nc) * 2));
                bh[np * 2][0] = r[0]; bh[np * 2][1] = r[1];
                bh[np * 2 + 1][0] = r[2]; bh[np * 2 + 1][1] = r[3];
                ldsm4t(&r[0], s2u((char*)W1Ls + (krg * 40 + nc) * 2));
                bl[np * 2][0] = r[0]; bl[np * 2][1] = r[1];
                bl[np * 2 + 1][0] = r[2]; bl[np * 2 + 1][1] = r[3];
            }
#pragma unroll
            for (int nt = 0; nt < 4; nt++) {
                mma_bf16(acc + nt * 4, &ah[0], &bh[nt][0]);
                mma_bf16(acc + nt * 4, &ah[0], &bl[nt][0]);
                mma_bf16(acc + nt * 4, &al[0], &bh[nt][0]);
            }
        }
        __syncwarp();
    }

    float* H2W = (float*)scr;
    {
        const int r0 = lane >> 2;
        const int cpair = (lane & 3) * 2;
#pragma unroll
        for (int nt = 0; nt < 4; nt++) {
            int cs = nt * 8 + cpair;
            float b0 = bw1[cs], b1 = bw1[cs + 1];
            float ga = gw2[cs], gb = gw2[cs + 1];
            float ba = betaw2[cs], bb = betaw2[cs + 1];
            float a00 = fmaxf(fmaf(ga, acc[nt * 4 + 0] + b0, ba), 0.f);
            float a01 = fmaxf(fmaf(gb, acc[nt * 4 + 1] + b1, bb), 0.f);
            float a10 = fmaxf(fmaf(ga, acc[nt * 4 + 2] + b0, ba), 0.f);
            float a11 = fmaxf(fmaf(gb, acc[nt * 4 + 3] + b1, bb), 0.f);
            *(float2*)&H2W[r0 * 36 + cs]       = make_float2(a00, a01);
            *(float2*)&H2W[(r0 + 8) * 36 + cs] = make_float2(a10, a11);
        }
    }
    __syncwarp();

    const int k0  = lane & 7;
    const int k1  = k0 + 8;
    const int cso = (lane >> 3) << 3;

#pragma unroll
    for (int i = 0; i < 16; i++) acc[i] = 0.f;
    {
        const float* x0p = H2W + k0 * 36;
        const float* x1p = H2W + k1 * 36;
#pragma unroll
        for (int cp = 0; cp < 32; cp += 4) {
            float4 ha = *(const float4*)(x0p + cp);
            float4 hb = *(const float4*)(x1p + cp);
            const float* wr = Ww2s + cp * 32 + cso;
            { const float4 u = *(const float4*)(wr); const float4 vv = *(const float4*)(wr + 4);
              FMA8(ha.x, u, vv, 0) FMA8(hb.x, u, vv, 8) }
            wr += 32;
            { const float4 u = *(const float4*)(wr); const float4 vv = *(const float4*)(wr + 4);
              FMA8(ha.y, u, vv, 0) FMA8(hb.y, u, vv, 8) }
            wr += 32;
            { const float4 u = *(const float4*)(wr); const float4 vv = *(const float4*)(wr + 4);
              FMA8(ha.z, u, vv, 0) FMA8(hb.z, u, vv, 8) }
            wr += 32;
            { const float4 u = *(const float4*)(wr); const float4 vv = *(const float4*)(wr + 4);
              FMA8(ha.w, u, vv, 0) FMA8(hb.w, u, vv, 8) }
        }
    }
    __syncwarp();

    float* WgW = (float*)scr;
    {
        float wa[8], wb[8];
#pragma unroll
        for (int i = 0; i < 8; i++) {
            int cs = cso + i;
            float la = acc[i]     + bw2[cs];
            float lb = acc[8 + i] + bw2[cs];
            float m = fmaxf(la, lb);
            m = fmaxf(m, __shfl_xor_sync(0xffffffffu, m, 1));
            m = fmaxf(m, __shfl_xor_sync(0xffffffffu, m, 2));
            m = fmaxf(m, __shfl_xor_sync(0xffffffffu, m, 4));
            float ea = __expf(la - m);
            float eb = __expf(lb - m);
            float s = ea + eb;
            s += __shfl_xor_sync(0xffffffffu, s, 1);
            s += __shfl_xor_sync(0xffffffffu, s, 2);
            s += __shfl_xor_sync(0xffffffffu, s, 4);
            float inv = 1.f / s;
            wa[i] = ea * inv;
            wb[i] = eb * inv;
        }
#pragma unroll
        for (int i = 0; i < 8; i++) {
            WgW[(cso + i) * 20 + k0] = wa[i];
            WgW[(cso + i) * 20 + k1] = wb[i];
        }
    }
    __syncwarp();

    float wk[16];
    {
        const float* wp = WgW + lane * 20;
        *(float4*)&wk[0]  = *(const float4*)(wp);
        *(float4*)&wk[4]  = *(const float4*)(wp + 4);
        *(float4*)&wk[8]  = *(const float4*)(wp + 8);
        *(float4*)&wk[12] = *(const float4*)(wp + 12);
    }

    float W0o[8], W1o[8], W2o[8], bpo[8], acc3[8];
#pragma unroll
    for (int cc = 0; cc < 8; cc++) {
        int c = cc * 32 + lane;
        W0o[cc] = Wp2[c];
        W1o[cc] = Wp2[256 + c];
        W2o[cc] = Wp2[512 + c];
        bpo[cc] = bp2[c];
        acc3[cc] = g_x[(size_t)P * CDIM + c];
    }

#pragma unroll 4
    for (int k = 0; k < KNN; k++) {
        int j = Js[w * 16 + k];
        float t0 = T3s[(w * 16 + k) * 4 + 0];
        float t1 = T3s[(w * 16 + k) * 4 + 1];
        float t2 = T3s[(w * 16 + k) * 4 + 2];
        const float* vrow = g_v + (size_t)j * CDIM;
        float wgt = wk[k];
#pragma unroll
        for (int cc = 0; cc < 8; cc++) {
            int c = cc * 32 + lane;
            float pr = fmaf(t0, W0o[cc], fmaf(t1, W1o[cc], fmaf(t2, W2o[cc], bpo[cc])));
            acc3[cc] = fmaf(vrow[c] + pr, wgt, acc3[cc]);
        }
    }

#pragma unroll
    for (int cc = 0; cc < 8; cc++)
        out[(size_t)P * CDIM + cc * 32 + lane] = acc3[cc];
}

// ---------------------------------------------------------------------------
// Launch — fork-join: high-priority kNN branch overlaps embed/conv/qkv chain.
// ---------------------------------------------------------------------------
extern "C" void kernel_launch(void* const* d_in, const int* in_sizes, int n_in,
                              void* d_out, int out_size)
{
    const float* x_main = (const float*)d_in[0];
    const float* x_mod  = (const float*)d_in[1];
    const float* xyz    = (const float*)d_in[2];
    const float* We2d   = (const float*)d_in[3];
    const float* be2d   = (const float*)d_in[4];
    const float* We3d   = (const float*)d_in[5];
    const float* be3d   = (const float*)d_in[6];
    const float* Wq     = (const float*)d_in[7];
    const float* bq     = (const float*)d_in[8];
    const float* Wk     = (const float*)d_in[9];
    const float* bk     = (const float*)d_in[10];
    const float* Wv     = (const float*)d_in[11];
    const float* bv     = (const float*)d_in[12];
    const float* Wp1    = (const float*)d_in[13];
    const float* bp1    = (const float*)d_in[14];
    const float* gp     = (const float*)d_in[15];
    const float* betap  = (const float*)d_in[16];
    const float* Wp2    = (const float*)d_in[17];
    const float* bp2    = (const float*)d_in[18];
    const float* gw1    = (const float*)d_in[19];
    const float* betaw1 = (const float*)d_in[20];
    const float* Ww1    = (const float*)d_in[21];
    const float* bw1    = (const float*)d_in[22];
    const float* gw2    = (const float*)d_in[23];
    const float* betaw2 = (const float*)d_in[24];
    const float* Ww2    = (const float*)d_in[25];
    const float* bw2    = (const float*)d_in[26];
    float* out = (float*)d_out;

    float *dx, *dq, *dk, *dv;
    cudaGetSymbolAddress((void**)&dx, g_x);
    cudaGetSymbolAddress((void**)&dq, g_q);
    cudaGetSymbolAddress((void**)&dk, g_k);
    cudaGetSymbolAddress((void**)&dv, g_v);

    cudaFuncSetAttribute(qkv_mma_kernel, cudaFuncAttributeMaxDynamicSharedMemorySize,
                         QKV_SMEM_BYTES);
    cudaFuncSetAttribute(attn_kernel, cudaFuncAttributeMaxDynamicSharedMemorySize,
                         ATTN_SMEM_BYTES);
    cudaFuncSetAttribute(knn_kernel, cudaFuncAttributeMaxDynamicSharedMemorySize,
                         KNN_SMEM_BYTES);

    // Lazy one-time stream/event setup (first call is the uncaptured
    // correctness run, so creation never happens during graph capture).
    static cudaStream_t sB = nullptr;
    static cudaEvent_t  evFork = nullptr, evJoin = nullptr;
    if (sB == nullptr) {
        int pLeast, pGreatest;
        cudaDeviceGetStreamPriorityRange(&pLeast, &pGreatest);
        cudaStreamCreateWithPriority(&sB, cudaStreamNonBlocking, pGreatest);
        cudaEventCreateWithFlags(&evFork, cudaEventDisableTiming);
        cudaEventCreateWithFlags(&evJoin, cudaEventDisableTiming);
    }

    // Fork
    cudaEventRecord(evFork, 0);
    cudaStreamWaitEvent(sB, evFork, 0);

    // Branch B (high priority): kNN partials + merge (needs only xyz)
    knn_kernel<<<dim3(NPTS / 128, NPART), 128, KNN_SMEM_BYTES, sB>>>(xyz);
    knn_merge_kernel<<<NPTS * 32 / 256, 256, 0, sB>>>();
    cudaEventRecord(evJoin, sB);

    // Main stream: merged embed (+ fused bf16), weight conversions, qkv
    sgemm_embed_kernel<<<dim3(NPTS / 128, 2), 256>>>(x_main, We3d, be3d,
                                                     x_mod,  We2d, be2d, dx);
    convert_w_kernel<<<CDIM * 768 / 256, 256>>>(Wq, Wk, Wv);
    convert_w1_kernel<<<CDIM * 32 / 256, 256>>>(Ww1);
    qkv_mma_kernel<<<dim3(NPTS / 128, 6), 256, QKV_SMEM_BYTES>>>(bq, bk, bv, dq, dk, dv);

    // Join: attn needs both branches
    cudaStreamWaitEvent(0, evJoin, 0);

    attn_kernel<<<NPTS / 8, 256, ATTN_SMEM_BYTES>>>(
        xyz, Wp1, bp1, gp, betap, Wp2, bp2, gw1, betaw1,
        bw1, gw2, betaw2, Ww2, bw2, out);
}